// round 15
// baseline (speedup 1.0000x reference)
#include <cuda_runtime.h>
#include <mma.h>
#include <math.h>
#include <float.h>

using namespace nvcuda;

#define BB 2
#define NN 2048
#define CC 128
#define KK 16
#define BN (BB*NN)
#define PP (BB*NN*KK)
#define EPSF 1e-6f
#define BNEPS 1e-5f

// ---------------- scratch pool ----------------
constexpr long F_SRCD   = 0;
constexpr long F_DSTD   = F_SRCD   + (long)BN*CC;
constexpr long F_NSQS   = F_DSTD   + (long)BN*CC;
constexpr long F_NSQD   = F_NSQS   + BN;
constexpr long F_NRMS   = F_NSQD   + BN;
constexpr long F_NRMD   = F_NRMS   + BN;
constexpr long F_MAXDS  = F_NRMD   + BN;
constexpr long F_MAXSD  = F_MAXDS  + BN;
constexpr long F_NRM2S  = F_MAXSD  + BN;
constexpr long F_NRM2D  = F_NRM2S  + BN;
constexpr long F_SDC    = F_NRM2D  + BN;
constexpr long F_DSC    = F_SDC    + PP;
constexpr long F_SDN    = F_DSC    + PP;
constexpr long F_DSN    = F_SDN    + PP;
constexpr long F_STATS  = F_DSN    + PP;            // 8 slots x 1024 (S at +0, Q at +512)
constexpr long F_W2P    = F_STATS  + 8*1024;        // padded+rounded c2_W0 [128][144]
constexpr long F_WC2    = F_W2P    + 128*144;       // rounded c2_W (2 x 128x128)
constexpr long F_WC10   = F_WC2    + 2*CC*CC;       // rounded c1_W0 (256x272)
constexpr long F_WC1    = F_WC10   + 256*272;       // rounded c1_W (2 x 256x256)
constexpr long F_WM1    = F_WC1    + 2*256*256;     // rounded m1_W
constexpr long F_WM2    = F_WM1    + 256*256;       // rounded m2_W
constexpr long F_IDX    = F_WM2    + 256*256;       // int
constexpr long F_SIDX   = F_IDX    + PP;
constexpr long F_DIDX   = F_SIDX   + PP;
constexpr long F_ATT    = F_DIDX   + PP;
constexpr long F_MB1    = F_ATT    + (long)BN*256;
constexpr long F_MB2    = F_MB1    + (long)BN*256;
constexpr long F_SRCNBR = F_MB2    + (long)BN*256;
constexpr long F_DSTNBR = F_SRCNBR + (long)BN*CC;
constexpr long F_INNER  = F_DSTNBR + (long)BN*CC;
constexpr long F_F      = F_INNER  + (long)BB*NN*NN;
constexpr long F_FSZ    = (long)2*PP*144;           // max(PP*272, 2PP*144)
constexpr long F_Y0     = F_F      + F_FSZ;
constexpr long F_Y1     = F_Y0     + (long)PP*256;
constexpr long F_END    = F_Y1     + (long)PP*256;

__device__ __align__(128) float g_pool[F_END];

__device__ __forceinline__ void atomicMaxF(float* a, float v) {
    if (!(v < 0.f)) atomicMax((int*)a, __float_as_int(v));
    else            atomicMin((unsigned int*)a, __float_as_uint(v));
}

__device__ __forceinline__ unsigned cvt_tf32(float x) {
    unsigned u;
    asm("cvt.rn.tf32.f32 %0, %1;" : "=r"(u) : "f"(x));
    return u;
}
__device__ __forceinline__ float round_tf32(float x) {
    return __uint_as_float(cvt_tf32(x));
}

__device__ __forceinline__ void cp_async16(unsigned saddr, const void* gptr) {
    asm volatile("cp.async.ca.shared.global [%0], [%1], 16;" :: "r"(saddr), "l"(gptr));
}
__device__ __forceinline__ void cp_commit() { asm volatile("cp.async.commit_group;"); }
template<int N> __device__ __forceinline__ void cp_wait() {
    asm volatile("cp.async.wait_group %0;" :: "n"(N));
}

__global__ void k_fill(float* __restrict__ p, float v, int n) {
    int i = blockIdx.x * blockDim.x + threadIdx.x;
    if (i < n) p[i] = v;
}

__global__ void k_cvt(const float* __restrict__ in, float* __restrict__ out, int n) {
    int i = blockIdx.x * blockDim.x + threadIdx.x;
    if (i < n) out[i] = round_tf32(in[i]);
}

__global__ void k_pad_w(const float* __restrict__ W, float* __restrict__ Wp) {
    int o = blockIdx.x; int k = threadIdx.x; // 144 threads
    Wp[o * 144 + k] = (k < 132) ? round_tf32(W[o * 132 + k]) : 0.f;
}

// both clouds: [B,C,N] -> [B,N,C] plus |.|^2 and |.|
__global__ void k_transpose_norm(const float* __restrict__ descS, const float* __restrict__ descD,
                                 float* __restrict__ dmatAll, float* __restrict__ nsqAll,
                                 float* __restrict__ nrmAll) {
    int cloud = blockIdx.y;
    const float* desc = cloud ? descD : descS;
    float* dmat = dmatAll + (long)cloud*BN*CC;
    float* nsq  = nsqAll  + cloud*BN;
    float* nrm  = nrmAll  + cloud*BN;
    int bn = blockIdx.x; int b = bn >> 11; int n = bn & (NN - 1);
    int c = threadIdx.x;
    float v = desc[((long)b*CC + c)*NN + n];
    dmat[(long)bn*CC + c] = v;
    float s = v * v;
    #pragma unroll
    for (int o = 16; o > 0; o >>= 1) s += __shfl_down_sync(0xffffffffu, s, o);
    __shared__ float ps[4];
    if ((c & 31) == 0) ps[c >> 5] = s;
    __syncthreads();
    if (c == 0) { float t = ps[0]+ps[1]+ps[2]+ps[3]; nsq[bn] = t; nrm[bn] = sqrtf(t); }
}

__global__ void k_rownorm(const float* __restrict__ dmat, float* __restrict__ nrm) {
    int bn = blockIdx.x; int c = threadIdx.x;
    float v = dmat[(long)bn*CC + c];
    float s = v * v;
    #pragma unroll
    for (int o = 16; o > 0; o >>= 1) s += __shfl_down_sync(0xffffffffu, s, o);
    __shared__ float ps[4];
    if ((c & 31) == 0) ps[c >> 5] = s;
    __syncthreads();
    if (c == 0) nrm[bn] = sqrtf(ps[0]+ps[1]+ps[2]+ps[3]);
}

// ---------------- split-tf32 sim GEMM: 3-stage cp.async, reg-side hi/lo ----------
#define SGM 128
#define SGN 64
#define SLD 20
#define SCLD 68
#define SSTG ((SGM+SGN)*SLD)

__global__ __launch_bounds__(256, 3)
void k_gemm_sim(const float* __restrict__ A, const float* __restrict__ Bm,
                float* __restrict__ Cm,
                const float* __restrict__ nrmA, const float* __restrict__ nrmB,
                float* __restrict__ maxDS, float* __restrict__ maxSD) {
    const int b = blockIdx.z;
    A  += (long)b * NN * CC;
    Bm += (long)b * NN * CC;
    Cm += (long)b * NN * NN;

    __shared__ __align__(16) float smem[3 * SSTG];
    float* Csm = smem;
    __shared__ float rns[SGM], rnd[SGN], rm[SGM], cmx[SGN];

    const int tid = threadIdx.x;
    const int lane = tid & 31;
    const int g   = lane >> 2;
    const int tig = lane & 3;
    const int wid = tid >> 5;
    const int wm = wid & 3;
    const int wn = wid >> 2;
    const long rowBase = (long)blockIdx.y * SGM;
    const int colBase = blockIdx.x * SGN;

    if (tid < SGM) { rns[tid] = nrmA[b*NN + rowBase + tid]; rm[tid] = -3.4e38f; }
    if (tid < SGN) { rnd[tid] = nrmB[b*NN + colBase + tid]; cmx[tid] = -3.4e38f; }

    const int srow = tid >> 2;
    const int kq = (tid & 3) * 4;
    unsigned sbase;
    asm("{ .reg .u64 t; cvta.to.shared.u64 t, %1; cvt.u32.u64 %0, t; }"
        : "=r"(sbase) : "l"(smem));

    auto issue = [&](int kc) {
        int buf = kc % 3;
        int k0 = kc * 16;
        const float* ga0 = &A[(rowBase + srow) * CC + k0 + kq];
        const float* ga1 = &A[(rowBase + srow + 64) * CC + k0 + kq];
        const float* gb  = &Bm[(long)(colBase + srow) * CC + k0 + kq];
        unsigned base = sbase + (unsigned)(buf * SSTG * 4);
        unsigned da0 = base + (unsigned)((srow * SLD + kq) * 4);
        unsigned da1 = da0 + 64u * SLD * 4u;
        unsigned db  = base + (unsigned)((SGM * SLD + srow * SLD + kq) * 4);
        cp_async16(da0, ga0);
        cp_async16(da1, ga1);
        cp_async16(db, gb);
        cp_commit();
    };

    float acc[2][4][4];
    #pragma unroll
    for (int i = 0; i < 2; i++)
        #pragma unroll
        for (int j = 0; j < 4; j++)
            #pragma unroll
            for (int t = 0; t < 4; t++)
                acc[i][j][t] = 0.f;

    const int nk = CC / 16;
    issue(0);
    issue(1);

    for (int kc = 0; kc < nk; kc++) {
        cp_wait<1>();
        __syncthreads();
        if (kc + 2 < nk) issue(kc + 2);
        const float* As = smem + (kc % 3) * SSTG;
        const float* Bs = As + SGM * SLD;
        #pragma unroll
        for (int ks = 0; ks < 2; ks++) {
            const int kb = ks * 8;
            unsigned bh0[4], bh1[4], bl0[4], bl1[4];
            #pragma unroll
            for (int nj = 0; nj < 4; nj++) {
                int nb = wn * 32 + nj * 8 + g;
                float w0 = Bs[nb * SLD + kb + tig];
                float w1 = Bs[nb * SLD + kb + tig + 4];
                unsigned h0 = cvt_tf32(w0), h1 = cvt_tf32(w1);
                bh0[nj] = h0; bh1[nj] = h1;
                bl0[nj] = cvt_tf32(w0 - __uint_as_float(h0));
                bl1[nj] = cvt_tf32(w1 - __uint_as_float(h1));
            }
            #pragma unroll
            for (int mi = 0; mi < 2; mi++) {
                int ar = wm * 32 + mi * 16;
                float v0 = As[(ar + g    ) * SLD + kb + tig];
                float v1 = As[(ar + g + 8) * SLD + kb + tig];
                float v2 = As[(ar + g    ) * SLD + kb + tig + 4];
                float v3 = As[(ar + g + 8) * SLD + kb + tig + 4];
                unsigned ah0 = cvt_tf32(v0), ah1 = cvt_tf32(v1);
                unsigned ah2 = cvt_tf32(v2), ah3 = cvt_tf32(v3);
                unsigned al0 = cvt_tf32(v0 - __uint_as_float(ah0));
                unsigned al1 = cvt_tf32(v1 - __uint_as_float(ah1));
                unsigned al2 = cvt_tf32(v2 - __uint_as_float(ah2));
                unsigned al3 = cvt_tf32(v3 - __uint_as_float(ah3));
                #pragma unroll
                for (int nj = 0; nj < 4; nj++) {
                    asm volatile(
                        "mma.sync.aligned.m16n8k8.row.col.f32.tf32.tf32.f32 "
                        "{%0,%1,%2,%3}, {%4,%5,%6,%7}, {%8,%9}, {%0,%1,%2,%3};"
                        : "+f"(acc[mi][nj][0]), "+f"(acc[mi][nj][1]),
                          "+f"(acc[mi][nj][2]), "+f"(acc[mi][nj][3])
                        : "r"(ah0), "r"(ah1), "r"(ah2), "r"(ah3),
                          "r"(bh0[nj]), "r"(bh1[nj]));
                    asm volatile(
                        "mma.sync.aligned.m16n8k8.row.col.f32.tf32.tf32.f32 "
                        "{%0,%1,%2,%3}, {%4,%5,%6,%7}, {%8,%9}, {%0,%1,%2,%3};"
                        : "+f"(acc[mi][nj][0]), "+f"(acc[mi][nj][1]),
                          "+f"(acc[mi][nj][2]), "+f"(acc[mi][nj][3])
                        : "r"(ah0), "r"(ah1), "r"(ah2), "r"(ah3),
                          "r"(bl0[nj]), "r"(bl1[nj]));
                    asm volatile(
                        "mma.sync.aligned.m16n8k8.row.col.f32.tf32.tf32.f32 "
                        "{%0,%1,%2,%3}, {%4,%5,%6,%7}, {%8,%9}, {%0,%1,%2,%3};"
                        : "+f"(acc[mi][nj][0]), "+f"(acc[mi][nj][1]),
                          "+f"(acc[mi][nj][2]), "+f"(acc[mi][nj][3])
                        : "r"(al0), "r"(al1), "r"(al2), "r"(al3),
                          "r"(bh0[nj]), "r"(bh1[nj]));
                }
            }
        }
    }
    __syncthreads();

    #pragma unroll
    for (int mi = 0; mi < 2; mi++) {
        int r0r = wm * 32 + mi * 16 + g;
        #pragma unroll
        for (int nj = 0; nj < 4; nj++) {
            int c0 = wn * 32 + nj * 8 + 2 * tig;
            Csm[r0r * SCLD + c0]           = acc[mi][nj][0];
            Csm[r0r * SCLD + c0 + 1]       = acc[mi][nj][1];
            Csm[(r0r + 8) * SCLD + c0]     = acc[mi][nj][2];
            Csm[(r0r + 8) * SCLD + c0 + 1] = acc[mi][nj][3];
        }
    }
    __syncthreads();

    const int ccol = tid & 63;
    const int r0 = tid >> 6;
    const float nd = rnd[ccol];
    float colmax = -3.4e38f;
    #pragma unroll 8
    for (int it = 0; it < 32; it++) {
        int r = r0 + it * 4;
        float v = Csm[r * SCLD + ccol];
        Cm[(rowBase + r) * NN + colBase + ccol] = v;
        float csv = v / (nd * rns[r] + EPSF);
        colmax = fmaxf(colmax, csv);
        float wmx = csv;
        #pragma unroll
        for (int o = 16; o > 0; o >>= 1) wmx = fmaxf(wmx, __shfl_down_sync(0xffffffffu, wmx, o));
        if (lane == 0) atomicMaxF(&rm[r], wmx);
    }
    atomicMaxF(&cmx[ccol], colmax);
    __syncthreads();
    if (tid < SGM) atomicMaxF(&maxDS[b*NN + rowBase + tid], rm[tid]);
    else if (tid < SGM + SGN) atomicMaxF(&maxSD[b*NN + colBase + (tid - SGM)], cmx[tid - SGM]);
}

// ---------------- TF32 conv GEMM v4 (unchanged from 1018us kernel) ----------
#define TCM 128
#define TCN 64
#define ALD 20
#define CLD 68
#define TSTG ((TCM+TCN)*ALD)

__global__ __launch_bounds__(256, 3)
void k_gemm_tc(const float* __restrict__ A, const float* __restrict__ Bm,
               float* __restrict__ Cm, int P, int O, int Kd,
               const float* __restrict__ affS, const float* __restrict__ affQ,
               const float* __restrict__ gP, const float* __restrict__ bP, float invP,
               float* __restrict__ statS, float* __restrict__ statQ, int splitRows) {
    __shared__ __align__(16) float smem[3 * TSTG];
    float* Csm = smem;
    __shared__ float cs[TCN], cq[TCN];
    __shared__ float sSc[256], sSh[256];

    const int tid = threadIdx.x;
    const int lane = tid & 31;
    const int g   = lane >> 2;
    const int tig = lane & 3;
    const int wid = tid >> 5;
    const int wm = wid & 3;
    const int wn = wid >> 2;
    const int rowBase = blockIdx.y * TCM;
    const int colBase = blockIdx.x * TCN;
    const bool aff = (affS != nullptr);
    const bool stats = (statS != nullptr);
    const int cloudA = (splitRows > 0 && rowBase >= splitRows) ? 1 : 0;
    const int statOff = cloudA * O;

    if (aff && tid < Kd && tid < 256) {
        int so = cloudA * Kd + tid;
        float mu  = affS[so] * invP;
        float var = fmaxf(affQ[so] * invP - mu * mu, 0.f);
        float s   = gP[tid] * rsqrtf(var + BNEPS);
        sSc[tid] = s;
        sSh[tid] = bP[tid] - mu * s;
    }
    if (stats && tid < TCN) { cs[tid] = 0.f; cq[tid] = 0.f; }

    const int srow = tid >> 2;
    const int kq = (tid & 3) * 4;
    unsigned sbase;
    asm("{ .reg .u64 t; cvta.to.shared.u64 t, %1; cvt.u32.u64 %0, t; }"
        : "=r"(sbase) : "l"(smem));

    auto issue = [&](int kc) {
        int buf = kc % 3;
        int k0 = kc * 16;
        const float* ga0 = &A[(long)(rowBase + srow) * Kd + k0 + kq];
        const float* ga1 = &A[(long)(rowBase + srow + 64) * Kd + k0 + kq];
        const float* gb  = &Bm[(long)(colBase + srow) * Kd + k0 + kq];
        unsigned base = sbase + (unsigned)(buf * TSTG * 4);
        unsigned da0 = base + (unsigned)((srow * ALD + kq) * 4);
        unsigned da1 = da0 + 64u * ALD * 4u;
        unsigned db  = base + (unsigned)((TCM * ALD + srow * ALD + kq) * 4);
        cp_async16(da0, ga0);
        cp_async16(da1, ga1);
        cp_async16(db, gb);
        cp_commit();
    };

    float acc[2][4][4];
    #pragma unroll
    for (int i = 0; i < 2; i++)
        #pragma unroll
        for (int j = 0; j < 4; j++)
            #pragma unroll
            for (int t = 0; t < 4; t++)
                acc[i][j][t] = 0.f;

    const int nk = Kd / 16;
    issue(0);
    issue(1);

    for (int kc = 0; kc < nk; kc++) {
        cp_wait<1>();
        __syncthreads();
        if (kc + 2 < nk) issue(kc + 2);
        const float* As = smem + (kc % 3) * TSTG;
        const float* Bs = As + TCM * ALD;
        const int k0 = kc * 16;
        #pragma unroll
        for (int ks = 0; ks < 2; ks++) {
            const int kb = ks * 8;
            unsigned b0[4], b1[4];
            #pragma unroll
            for (int nj = 0; nj < 4; nj++) {
                int nb = wn * 32 + nj * 8 + g;
                b0[nj] = __float_as_uint(Bs[nb * ALD + kb + tig]);
                b1[nj] = __float_as_uint(Bs[nb * ALD + kb + tig + 4]);
            }
            float sc0 = 1.f, sh0 = 0.f, sc4 = 1.f, sh4 = 0.f;
            if (aff) {
                sc0 = sSc[k0 + kb + tig];     sh0 = sSh[k0 + kb + tig];
                sc4 = sSc[k0 + kb + tig + 4]; sh4 = sSh[k0 + kb + tig + 4];
            }
            #pragma unroll
            for (int mi = 0; mi < 2; mi++) {
                int ar = wm * 32 + mi * 16;
                float v0 = As[(ar + g    ) * ALD + kb + tig];
                float v1 = As[(ar + g + 8) * ALD + kb + tig];
                float v2 = As[(ar + g    ) * ALD + kb + tig + 4];
                float v3 = As[(ar + g + 8) * ALD + kb + tig + 4];
                unsigned a0, a1, a2, a3;
                if (aff) {
                    a0 = cvt_tf32(fmaxf(v0 * sc0 + sh0, 0.f));
                    a1 = cvt_tf32(fmaxf(v1 * sc0 + sh0, 0.f));
                    a2 = cvt_tf32(fmaxf(v2 * sc4 + sh4, 0.f));
                    a3 = cvt_tf32(fmaxf(v3 * sc4 + sh4, 0.f));
                } else {
                    a0 = __float_as_uint(v0);
                    a1 = __float_as_uint(v1);
                    a2 = __float_as_uint(v2);
                    a3 = __float_as_uint(v3);
                }
                #pragma unroll
                for (int nj = 0; nj < 4; nj++) {
                    asm volatile(
                        "mma.sync.aligned.m16n8k8.row.col.f32.tf32.tf32.f32 "
                        "{%0,%1,%2,%3}, {%4,%5,%6,%7}, {%8,%9}, {%0,%1,%2,%3};"
                        : "+f"(acc[mi][nj][0]), "+f"(acc[mi][nj][1]),
                          "+f"(acc[mi][nj][2]), "+f"(acc[mi][nj][3])
                        : "r"(a0), "r"(a1), "r"(a2), "r"(a3),
                          "r"(b0[nj]), "r"(b1[nj]));
                }
            }
        }
    }
    __syncthreads();

    #pragma unroll
    for (int mi = 0; mi < 2; mi++) {
        int r0r = wm * 32 + mi * 16 + g;
        #pragma unroll
        for (int nj = 0; nj < 4; nj++) {
            int c0 = wn * 32 + nj * 8 + 2 * tig;
            Csm[r0r * CLD + c0]           = acc[mi][nj][0];
            Csm[r0r * CLD + c0 + 1]       = acc[mi][nj][1];
            Csm[(r0r + 8) * CLD + c0]     = acc[mi][nj][2];
            Csm[(r0r + 8) * CLD + c0 + 1] = acc[mi][nj][3];
        }
    }
    __syncthreads();

    const int ccol = tid & 63;
    const int r0 = tid >> 6;
    float s = 0.f, q = 0.f;
    #pragma unroll 8
    for (int it = 0; it < 32; it++) {
        int r = r0 + it * 4;
        float v = Csm[r * CLD + ccol];
        Cm[(long)(rowBase + r) * O + colBase + ccol] = v;
        s += v; q += v * v;
    }
    if (stats) {
        atomicAdd(&cs[ccol], s);
        atomicAdd(&cq[ccol], q);
        __syncthreads();
        if (tid < TCN) {
            atomicAdd(&statS[statOff + colBase + tid], cs[tid]);
            atomicAdd(&statQ[statOff + colBase + tid], cq[tid]);
        }
    }
}

// ---------------- register-resident top-16: per-warp tournament + warp0 merge ------
// Each of 256 threads owns 8 candidates in registers (global idx = tid + 256*j).
// Stage 1: each warp extracts its top-16 by warp argmin rounds (no barriers).
// Stage 2: warp 0 merges 8x16=128 candidates. One barrier total.
__device__ __forceinline__ void topk_regs(float v[8], int* outIdx) {
    __shared__ float cv[128];
    __shared__ int   ci[128];
    const int tid = threadIdx.x, lane = tid & 31, w = tid >> 5;

    #pragma unroll 1
    for (int kk = 0; kk < KK; kk++) {
        float best = 3.4e38f; int bs = 0;
        #pragma unroll
        for (int j = 0; j < 8; j++)
            if (v[j] < best) { best = v[j]; bs = j; }
        int bi = tid + (bs << 8);
        float bv = best; int bgi = bi;
        #pragma unroll
        for (int o = 16; o > 0; o >>= 1) {
            float ov = __shfl_down_sync(0xffffffffu, bv, o);
            int   oi = __shfl_down_sync(0xffffffffu, bgi, o);
            if (ov < bv || (ov == bv && oi < bgi)) { bv = ov; bgi = oi; }
        }
        bv  = __shfl_sync(0xffffffffu, bv, 0);
        bgi = __shfl_sync(0xffffffffu, bgi, 0);
        if (lane == 0) { cv[w * KK + kk] = bv; ci[w * KK + kk] = bgi; }
        if (bgi == bi) v[bs] = 3.4e38f;
    }
    __syncthreads();
    if (w == 0) {
        float mv[4]; int mi[4];
        #pragma unroll
        for (int j = 0; j < 4; j++) { mv[j] = cv[lane + 32*j]; mi[j] = ci[lane + 32*j]; }
        #pragma unroll 1
        for (int kk = 0; kk < KK; kk++) {
            float best = 3.4e38f; int bgi = 0x7fffffff, bs = 0;
            #pragma unroll
            for (int j = 0; j < 4; j++)
                if (mv[j] < best || (mv[j] == best && mi[j] < bgi)) {
                    best = mv[j]; bgi = mi[j]; bs = j;
                }
            float bv = best; int bg = bgi;
            #pragma unroll
            for (int o = 16; o > 0; o >>= 1) {
                float ov = __shfl_down_sync(0xffffffffu, bv, o);
                int   oi = __shfl_down_sync(0xffffffffu, bg, o);
                if (ov < bv || (ov == bv && oi < bg)) { bv = ov; bg = oi; }
            }
            bv = __shfl_sync(0xffffffffu, bv, 0);
            bg = __shfl_sync(0xffffffffu, bg, 0);
            if (bg == bgi && bv == best) mv[bs] = 3.4e38f;
            if (lane == 0) outIdx[kk] = bg;
        }
    }
}

__global__ void k_knn_desc(const float* __restrict__ inner, const float* __restrict__ nsqS,
                           const float* __restrict__ nsqD, int* __restrict__ idxOut) {
    int n = blockIdx.x, b = blockIdx.y;
    const float* row = inner + (long)b*NN*NN + (long)n*NN;
    float q = nsqS[b*NN + n];
    int tid = threadIdx.x;
    float v[8];
    #pragma unroll
    for (int j = 0; j < 8; j++) {
        int m = tid + 256 * j;
        v[j] = q + nsqD[b*NN + m] - 2.f * row[m];
    }
    topk_regs(v, idxOut + ((long)b*NN + n) * KK);
}

__global__ void k_knn_xyz(const float* __restrict__ xyzS, const float* __restrict__ xyzD,
                          int* __restrict__ idxAll) {
    int n = blockIdx.x, b = blockIdx.y, cloud = blockIdx.z;
    const float* xyz = cloud ? xyzD : xyzS;
    int* idxOut = idxAll + (long)cloud*PP;
    long base = (long)b * NN * 3;
    float qx = xyz[base + (long)n*3], qy = xyz[base + (long)n*3+1], qz = xyz[base + (long)n*3+2];
    float qq = qx*qx + qy*qy + qz*qz;
    int tid = threadIdx.x;
    float v[8];
    #pragma unroll
    for (int j = 0; j < 8; j++) {
        int m = tid + 256 * j;
        float rx = xyz[base + (long)m*3], ry = xyz[base + (long)m*3+1], rz = xyz[base + (long)m*3+2];
        v[j] = qq + rx*rx + ry*ry + rz*rz - 2.f*(qx*rx + qy*ry + qz*rz);
    }
    topk_regs(v, idxOut + ((long)b*NN + n) * KK);
}

__global__ void k_simgather(const float* __restrict__ inner, const float* __restrict__ nrmS,
                            const float* __restrict__ nrmD, const float* __restrict__ maxDS,
                            const float* __restrict__ maxSD, const int* __restrict__ idx,
                            float* __restrict__ outSD, float* __restrict__ outDS) {
    int t = blockIdx.x * 256 + threadIdx.x;
    if (t >= PP) return;
    int b = t / (NN * KK);
    int n = (t / KK) & (NN - 1);
    int m = idx[t];
    float v  = inner[(long)b*NN*NN + (long)n*NN + m];
    float cs = v / (nrmD[b*NN + m] * nrmS[b*NN + n] + EPSF);
    outSD[t] = cs / (maxDS[b*NN + n] + EPSF);
    outDS[t] = cs / (maxSD[b*NN + m] + EPSF);
}

// both clouds: nbr conv input, tf32-ROUNDED (feeds non-affine GEMM), parallel tail
__global__ void k_build_nbr_f(const float* __restrict__ xyzS, const float* __restrict__ xyzD,
                              const float* __restrict__ dmatAll, const int* __restrict__ idxAll,
                              float* __restrict__ f) {
    int p = blockIdx.x;
    int cloud = p >= PP;
    int pl = p - cloud * PP;
    const float* xyz = cloud ? xyzD : xyzS;
    const float* dmatC = dmatAll + (long)cloud*BN*CC;
    int n = (pl / KK) & (NN - 1);
    int b = pl / (NN * KK);
    int m = idxAll[p];
    const float* dr = dmatC + ((long)b*NN + m) * CC;
    float* fo = f + (long)p * 144;
    int tid = threadIdx.x;
    fo[tid] = round_tf32(dr[tid]);
    if (tid < 16) {
        float val = 0.f;
        if (tid < 4) {
            long qb = ((long)b*NN + n) * 3, rb = ((long)b*NN + m) * 3;
            float rx = xyz[rb]-xyz[qb], ry = xyz[rb+1]-xyz[qb+1], rz = xyz[rb+2]-xyz[qb+2];
            float t;
            if (tid == 0) t = rx; else if (tid == 1) t = ry;
            else if (tid == 2) t = rz; else t = sqrtf(rx*rx+ry*ry+rz*rz);
            val = round_tf32(t);
        }
        fo[128 + tid] = val;
    }
}

// both clouds: grid 2*BN, in-block affine from producer stats
__global__ void k_nbr_final(const float* __restrict__ yraw,
                            const float* __restrict__ affS, const float* __restrict__ affQ,
                            const float* __restrict__ gP, const float* __restrict__ bP, float invP,
                            const int* __restrict__ idxAll,
                            const float* __restrict__ dmatAll, float* __restrict__ outAll) {
    int gblk = blockIdx.x;
    int cloud = gblk >= BN;
    int bn = gblk - cloud * BN;
    const float* y = yraw + (long)cloud*PP*CC;
    const int* idx = idxAll + (long)cloud*PP;
    const float* dmat = dmatAll + (long)cloud*BN*CC;
    float* outN = outAll + (long)cloud*BN*CC;
    int tid = threadIdx.x;
    __shared__ float fe[KK][CC];
    __shared__ float mk[KK], wgt[KK];
    __shared__ int sid[KK];
    __shared__ float sSc[CC], sSh[CC];
    if (tid < CC) {
        int so = cloud * CC + tid;
        float mu  = affS[so] * invP;
        float var = fmaxf(affQ[so] * invP - mu * mu, 0.f);
        float s   = gP[tid] * rsqrtf(var + BNEPS);
        sSc[tid] = s;
        sSh[tid] = bP[tid] - mu * s;
    }
    if (tid < KK) sid[tid] = idx[(long)bn*KK + tid];
    __syncthreads();
    for (int t = tid; t < KK * CC; t += 256) {
        int k = t >> 7, c = t & 127;
        float v = y[((long)bn*KK + k) * CC + c];
        fe[k][c] = fmaxf(v * sSc[c] + sSh[c], 0.f);
    }
    __syncthreads();
    int w = tid >> 5, lane = tid & 31;
    for (int kk = w; kk < KK; kk += 8) {
        float mx = -3.4e38f;
        for (int c = lane; c < CC; c += 32) mx = fmaxf(mx, fe[kk][c]);
        #pragma unroll
        for (int o = 16; o > 0; o >>= 1) mx = fmaxf(mx, __shfl_down_sync(0xffffffffu, mx, o));
        if (lane == 0) mk[kk] = mx;
    }
    __syncthreads();
    if (tid == 0) {
        float m = -3.4e38f;
        for (int k = 0; k < KK; k++) m = fmaxf(m, mk[k]);
        float s = 0.f;
        for (int k = 0; k < KK; k++) { float e = expf(mk[k]-m); wgt[k] = e; s += e; }
        float r = 1.f / s;
        for (int k = 0; k < KK; k++) wgt[k] *= r;
    }
    __syncthreads();
    if (tid < CC) {
        int b = bn >> 11;
        float a = 0.f;
        #pragma unroll
        for (int k = 0; k < KK; k++) a += wgt[k] * dmat[((long)b*NN + sid[k]) * CC + tid];
        outN[(long)bn*CC + tid] = a;
    }
}

// main feats build (272 ch), tf32-ROUNDED, parallel tail
__global__ void k_build_feats(const float* __restrict__ src_xyz, const float* __restrict__ dst_xyz,
                              const float* __restrict__ srcd, const float* __restrict__ dstd,
                              const float* __restrict__ srcw, const float* __restrict__ dstw,
                              const float* __restrict__ sdc, const float* __restrict__ dsc,
                              const float* __restrict__ sdn, const float* __restrict__ dsn,
                              const int* __restrict__ idx, float* __restrict__ feats) {
    int p = blockIdx.x;
    int n = (p / KK) & (NN - 1);
    int b = p / (NN * KK);
    int m = idx[p];
    float* fo = feats + (long)p * 272;
    int tid = threadIdx.x;
    fo[10 + tid]  = round_tf32(srcd[((long)b*NN + n) * CC + tid]);
    fo[138 + tid] = round_tf32(dstd[((long)b*NN + m) * CC + tid]);
    if (tid < 16) {
        long qb = ((long)b*NN + n) * 3, rb = ((long)b*NN + m) * 3;
        float t;
        if (tid < 10) {
            float sx = src_xyz[qb], sy = src_xyz[qb+1], sz = src_xyz[qb+2];
            float kx = dst_xyz[rb], ky = dst_xyz[rb+1], kz = dst_xyz[rb+2];
            float rx = kx-sx, ry = ky-sy, rz = kz-sz;
            switch (tid) {
                case 0: t = rx; break;
                case 1: t = ry; break;
                case 2: t = rz; break;
                case 3: t = sqrtf(rx*rx+ry*ry+rz*rz); break;
                case 4: t = sx; break;
                case 5: t = sy; break;
                case 6: t = sz; break;
                case 7: t = kx; break;
                case 8: t = ky; break;
                default: t = kz; break;
            }
            fo[tid] = round_tf32(t);
        } else {
            switch (tid) {
                case 10: t = srcw[b*NN+n]; break;
                case 11: t = dstw[b*NN+m]; break;
                case 12: t = sdc[p]; break;
                case 13: t = dsc[p]; break;
                case 14: t = sdn[p]; break;
                default: t = dsn[p]; break;
            }
            fo[256 + tid] = round_tf32(t);   // 266..271
        }
    }
}

__global__ void k_attention(const float* __restrict__ yraw,
                            const float* __restrict__ affS, const float* __restrict__ affQ,
                            const float* __restrict__ gP, const float* __restrict__ bP, float invP,
                            const int* __restrict__ idx, const float* __restrict__ dst_xyz,
                            float* __restrict__ outC, float* __restrict__ att) {
    int bn = blockIdx.x, tid = threadIdx.x;
    __shared__ float fe[KK][256];
    __shared__ float mk[KK], wgt[KK];
    __shared__ int sid[KK];
    if (tid < KK) sid[tid] = idx[(long)bn*KK + tid];
    float mu  = affS[tid] * invP;
    float var = fmaxf(affQ[tid] * invP - mu * mu, 0.f);
    float s   = gP[tid] * rsqrtf(var + BNEPS);
    float h   = bP[tid] - mu * s;
    #pragma unroll
    for (int k = 0; k < KK; k++) {
        float v = yraw[((long)bn*KK + k) * 256 + tid];
        fe[k][tid] = fmaxf(v * s + h, 0.f);
    }
    __syncthreads();
    int w = tid >> 5, lane = tid & 31;
    for (int kk = w; kk < KK; kk += 8) {
        float mx = -3.4e38f;
        for (int c = lane; c < 256; c += 32) mx = fmaxf(mx, fe[kk][c]);
        #pragma unroll
        for (int o = 16; o > 0; o >>= 1) mx = fmaxf(mx, __shfl_down_sync(0xffffffffu, mx, o));
        if (lane == 0) mk[kk] = mx;
    }
    __syncthreads();
    if (tid == 0) {
        float m = -3.4e38f;
        for (int k = 0; k < KK; k++) m = fmaxf(m, mk[k]);
        float ssum = 0.f;
        for (int k = 0; k < KK; k++) { float e = expf(mk[k]-m); wgt[k] = e; ssum += e; }
        float r = 1.f / ssum;
        for (int k = 0; k < KK; k++) wgt[k] *= r;
    }
    __syncthreads();
    float a = 0.f;
    #pragma unroll
    for (int k = 0; k < KK; k++) a += wgt[k] * fe[k][tid];
    att[(long)bn * 256 + tid] = round_tf32(a);
    if (tid < 3) {
        int b = bn >> 11;
        float cg = 0.f;
        #pragma unroll
        for (int k = 0; k < KK; k++)
            cg += wgt[k] * dst_xyz[((long)b*NN + sid[k]) * 3 + tid];
        outC[(long)bn * 3 + tid] = cg;
    }
}

__global__ void k_mlp3(const float* __restrict__ yraw,
                       const float* __restrict__ affS, const float* __restrict__ affQ,
                       const float* __restrict__ gP, const float* __restrict__ bP, float invP,
                       const float* __restrict__ w3, const float* __restrict__ b3,
                       float* __restrict__ outw) {
    int bn = blockIdx.x, tid = threadIdx.x;
    float mu  = affS[tid] * invP;
    float var = fmaxf(affQ[tid] * invP - mu * mu, 0.f);
    float s   = gP[tid] * rsqrtf(var + BNEPS);
    float h   = bP[tid] - mu * s;
    float v = fmaxf(yraw[(long)bn*256 + tid] * s + h, 0.f) * w3[tid];
    #pragma unroll
    for (int o = 16; o > 0; o >>= 1) v += __shfl_down_sync(0xffffffffu, v, o);
    __shared__ float ps[8];
    if ((tid & 31) == 0) ps[tid >> 5] = v;
    __syncthreads();
    if (tid == 0) {
        float s2 = 0.f;
        #pragma unroll
        for (int i = 0; i < 8; i++) s2 += ps[i];
        outw[bn] = 1.f / (1.f + expf(-(s2 + b3[0])));
    }
}

extern "C" void kernel_launch(void* const* d_in, const int* in_sizes, int n_in,
                              void* d_out, int out_size) {
    const float* src_xyz  = (const float*)d_in[0];
    const float* src_desc = (const float*)d_in[1];
    const float* dst_xyz  = (const float*)d_in[2];
    const float* dst_desc = (const float*)d_in[3];
    const float* src_w    = (const float*)d_in[4];
    const float* dst_w    = (const float*)d_in[5];
    const float* c1_W0 = (const float*)d_in[6];
    const float* c1_W  = (const float*)d_in[7];
    const float* c1_g  = (const float*)d_in[8];
    const float* c1_b  = (const float*)d_in[9];
    const float* c2_W0 = (const float*)d_in[10];
    const float* c2_W  = (const float*)d_in[11];
    const float* c2_g  = (const float*)d_in[12];
    const float* c2_b  = (const float*)d_in[13];
    const float* m1_W  = (const float*)d_in[14];
    const float* m1_g  = (const float*)d_in[16];
    const float* m1_b  = (const float*)d_in[17];
    const float* m2_W  = (const float*)d_in[18];
    const float* m2_g  = (const float*)d_in[20];
    const float* m2_b  = (const float*)d_in[21];
    const float* m3_W  = (const float*)d_in[22];
    const float* m3_b  = (const float*)d_in[23];

    float* base = nullptr;
    cudaGetSymbolAddress((void**)&base, g_pool);
    float* srcd   = base + F_SRCD;
    float* dstd   = base + F_DSTD;
    float* nsqS   = base + F_NSQS;
    float* nsqD   = base + F_NSQD;
    float* nrmS   = base + F_NRMS;
    float* nrmD   = base + F_NRMD;
    float* maxDS  = base + F_MAXDS;
    float* maxSD  = base + F_MAXSD;
    float* nrm2S  = base + F_NRM2S;
    float* nrm2D  = base + F_NRM2D;
    float* sdc    = base + F_SDC;
    float* dsc    = base + F_DSC;
    float* sdn    = base + F_SDN;
    float* dsn    = base + F_DSN;
    float* stat0  = base + F_STATS;
    float* w2p    = base + F_W2P;
    float* wc2    = base + F_WC2;
    float* wc10   = base + F_WC10;
    float* wc1    = base + F_WC1;
    float* wm1    = base + F_WM1;
    float* wm2    = base + F_WM2;
    int*   idx    = (int*)(base + F_IDX);
    int*   sidx   = (int*)(base + F_SIDX);
    float* att    = base + F_ATT;
    float* mb1    = base + F_MB1;
    float* mb2    = base + F_MB2;
    float* srcnbr = base + F_SRCNBR;
    float* inner  = base + F_INNER;
    float* fbuf   = base + F_F;
    float* y0     = base + F_Y0;
    float* y1     = base + F_Y1;
    float* outC   = (float*)d_out;
    float* outW   = (float*)d_out + (long)BB*NN*3;

    auto slot = [&](int i) { return stat0 + (long)i * 1024; };
    const float invPP = 1.f / (float)PP;
    const float invBN = 1.f / (float)BN;

    // setup
    k_fill<<<32, 256>>>(stat0, 0.f, 8 * 1024);
    k_pad_w<<<128, 144>>>(c2_W0, w2p);
    k_cvt<<<(2*CC*CC+255)/256, 256>>>(c2_W, wc2, 2*CC*CC);
    k_cvt<<<(256*272+255)/256, 256>>>(c1_W0, wc10, 256*272);
    k_cvt<<<(2*256*256+255)/256, 256>>>(c1_W, wc1, 2*256*256);
    k_cvt<<<(256*256+255)/256, 256>>>(m1_W, wm1, 256*256);
    k_cvt<<<(256*256+255)/256, 256>>>(m2_W, wm2, 256*256);

    // A: transpose + norms
    k_transpose_norm<<<dim3(BN, 2), 128>>>(src_desc, dst_desc, srcd, nsqS, nrmS);

    // inner = src . dst with fused cosine maxes
    k_fill<<<32, 256>>>(maxDS, -3.4e38f, 2*BN);
    k_gemm_sim<<<dim3(NN/SGN, NN/SGM, 2), 256>>>(srcd, dstd, inner, nrmS, nrmD, maxDS, maxSD);
    k_knn_desc<<<dim3(NN, BB), 256>>>(inner, nsqS, nsqD, idx);
    k_simgather<<<PP/256, 256>>>(inner, nrmS, nrmD, maxDS, maxSD, idx, sdc, dsc);

    // B: neighborhood descriptors — both clouds batched
    k_knn_xyz<<<dim3(NN, BB, 2), 256>>>(src_xyz, dst_xyz, sidx);
    k_build_nbr_f<<<2*PP, 128>>>(src_xyz, dst_xyz, srcd, sidx, fbuf);
    k_gemm_tc<<<dim3(CC/TCN, (2*PP)/TCM), 256>>>(fbuf, w2p, y0, 2*PP, CC, 144,
        nullptr, nullptr, nullptr, nullptr, 0.f, slot(0), slot(0)+512, PP);
    k_gemm_tc<<<dim3(CC/TCN, (2*PP)/TCM), 256>>>(y0, wc2, y1, 2*PP, CC, CC,
        slot(0), slot(0)+512, c2_g, c2_b, invPP, slot(1), slot(1)+512, PP);
    k_gemm_tc<<<dim3(CC/TCN, (2*PP)/TCM), 256>>>(y1, wc2 + CC*CC, y0, 2*PP, CC, CC,
        slot(1), slot(1)+512, c2_g + CC, c2_b + CC, invPP, slot(2), slot(2)+512, PP);
    k_nbr_final<<<2*BN, 256>>>(y0, slot(2), slot(2)+512, c2_g + 2*CC, c2_b + 2*CC, invPP,
                               sidx, srcd, srcnbr);

    // nbr cosine sims
    k_rownorm<<<2*BN, 128>>>(srcnbr, nrm2S);
    k_fill<<<32, 256>>>(maxDS, -3.4e38f, 2*BN);
    k_gemm_sim<<<dim3(NN/SGN, NN/SGM, 2), 256>>>(srcnbr, srcnbr + (long)BN*CC, inner,
                                                 nrm2S, nrm2D, maxDS, maxSD);
    k_simgather<<<PP/256, 256>>>(inner, nrm2S, nrm2D, maxDS, maxSD, idx, sdn, dsn);

    // C: main feature conv + attention
    k_build_feats<<<PP, 128>>>(src_xyz, dst_xyz, srcd, dstd, src_w, dst_w,
                               sdc, dsc, sdn, dsn, idx, fbuf);
    k_gemm_tc<<<dim3(256/TCN, PP/TCM), 256>>>(fbuf, wc10, y0, PP, 256, 272,
        nullptr, nullptr, nullptr, nullptr, 0.f, slot(3), slot(3)+512, 0);
    k_gemm_tc<<<dim3(256/TCN, PP/TCM), 256>>>(y0, wc1, y1, PP, 256, 256,
        slot(3), slot(3)+512, c1_g, c1_b, invPP, slot(4), slot(4)+512, 0);
    k_gemm_tc<<<dim3(256/TCN, PP/TCM), 256>>>(y1, wc1 + 256*256, y0, PP, 256, 256,
        slot(4), slot(4)+512, c1_g + 256, c1_b + 256, invPP, slot(5), slot(5)+512, 0);
    k_attention<<<BN, 256>>>(y0, slot(5), slot(5)+512, c1_g + 512, c1_b + 512, invPP,
                             idx, dst_xyz, outC, att);

    // D: MLP head
    k_gemm_tc<<<dim3(256/TCN, BN/TCM), 256>>>(att, wm1, mb1, BN, 256, 256,
        nullptr, nullptr, nullptr, nullptr, 0.f, slot(6), slot(6)+512, 0);
    k_gemm_tc<<<dim3(256/TCN, BN/TCM), 256>>>(mb1, wm2, mb2, BN, 256, 256,
        slot(6), slot(6)+512, m1_g, m1_b, invBN, slot(7), slot(7)+512, 0);
    k_mlp3<<<BN, 256>>>(mb2, slot(7), slot(7)+512, m2_g, m2_b, invBN, m3_W, m3_b, outW);
}

// round 16
// speedup vs baseline: 1.0265x; 1.0265x over previous
#include <cuda_runtime.h>
#include <mma.h>
#include <math.h>
#include <float.h>

using namespace nvcuda;

#define BB 2
#define NN 2048
#define CC 128
#define KK 16
#define BN (BB*NN)
#define PP (BB*NN*KK)
#define EPSF 1e-6f
#define BNEPS 1e-5f

// ---------------- scratch pool ----------------
constexpr long F_SRCD   = 0;
constexpr long F_DSTD   = F_SRCD   + (long)BN*CC;
constexpr long F_NSQS   = F_DSTD   + (long)BN*CC;
constexpr long F_NSQD   = F_NSQS   + BN;
constexpr long F_NRMS   = F_NSQD   + BN;
constexpr long F_NRMD   = F_NRMS   + BN;
constexpr long F_MAXDS  = F_NRMD   + BN;
constexpr long F_MAXSD  = F_MAXDS  + BN;
constexpr long F_MAXD2  = F_MAXSD  + BN;   // round-2 sim maxes (own buffers: fill folds into setup)
constexpr long F_MAXS2  = F_MAXD2  + BN;
constexpr long F_NRM2S  = F_MAXS2  + BN;
constexpr long F_NRM2D  = F_NRM2S  + BN;
constexpr long F_SDC    = F_NRM2D  + BN;
constexpr long F_DSC    = F_SDC    + PP;
constexpr long F_SDN    = F_DSC    + PP;
constexpr long F_DSN    = F_SDN    + PP;
constexpr long F_STATS  = F_DSN    + PP;            // 8 slots x 1024 (S at +0, Q at +512)
constexpr long F_W2P    = F_STATS  + 8*1024;        // padded+rounded c2_W0 [128][144]
constexpr long F_WC2    = F_W2P    + 128*144;       // rounded c2_W (2 x 128x128)
constexpr long F_WC10   = F_WC2    + 2*CC*CC;       // rounded c1_W0 (256x272)
constexpr long F_WC1    = F_WC10   + 256*272;       // rounded c1_W (2 x 256x256)
constexpr long F_WM1    = F_WC1    + 2*256*256;     // rounded m1_W
constexpr long F_WM2    = F_WM1    + 256*256;       // rounded m2_W
constexpr long F_IDX    = F_WM2    + 256*256;       // int
constexpr long F_SIDX   = F_IDX    + PP;
constexpr long F_DIDX   = F_SIDX   + PP;
constexpr long F_ATT    = F_DIDX   + PP;
constexpr long F_MB1    = F_ATT    + (long)BN*256;
constexpr long F_MB2    = F_MB1    + (long)BN*256;
constexpr long F_SRCNBR = F_MB2    + (long)BN*256;
constexpr long F_DSTNBR = F_SRCNBR + (long)BN*CC;
constexpr long F_INNER  = F_DSTNBR + (long)BN*CC;
constexpr long F_F      = F_INNER  + (long)BB*NN*NN;
constexpr long F_FSZ    = (long)2*PP*144;           // max(PP*272, 2PP*144)
constexpr long F_Y0     = F_F      + F_FSZ;
constexpr long F_Y1     = F_Y0     + (long)PP*256;
constexpr long F_END    = F_Y1     + (long)PP*256;

__device__ __align__(128) float g_pool[F_END];

__device__ __forceinline__ void atomicMaxF(float* a, float v) {
    if (!(v < 0.f)) atomicMax((int*)a, __float_as_int(v));
    else            atomicMin((unsigned int*)a, __float_as_uint(v));
}

__device__ __forceinline__ unsigned cvt_tf32(float x) {
    unsigned u;
    asm("cvt.rn.tf32.f32 %0, %1;" : "=r"(u) : "f"(x));
    return u;
}
__device__ __forceinline__ float round_tf32(float x) {
    return __uint_as_float(cvt_tf32(x));
}

__device__ __forceinline__ void cp_async16(unsigned saddr, const void* gptr) {
    asm volatile("cp.async.ca.shared.global [%0], [%1], 16;" :: "r"(saddr), "l"(gptr));
}
__device__ __forceinline__ void cp_commit() { asm volatile("cp.async.commit_group;"); }
template<int N> __device__ __forceinline__ void cp_wait() {
    asm volatile("cp.async.wait_group %0;" :: "n"(N));
}

// ---------------- single setup kernel: stat zero, max fills (both rounds), weight rounding ----
#define SETUP_N (8192 + 2*BN + 2*BN + 128*144 + 2*CC*CC + 256*272 + 2*256*256 + 256*256 + 256*256)

__global__ void k_setup(const float* __restrict__ c2W0, const float* __restrict__ c2W,
                        const float* __restrict__ c1W0, const float* __restrict__ c1W,
                        const float* __restrict__ m1W, const float* __restrict__ m2W) {
    long i = (long)blockIdx.x * 256 + threadIdx.x;
    if (i < 8192) { g_pool[F_STATS + i] = 0.f; return; }
    i -= 8192;
    if (i < 2*BN) { g_pool[F_MAXDS + i] = -3.4e38f; return; }
    i -= 2*BN;
    if (i < 2*BN) { g_pool[F_MAXD2 + i] = -3.4e38f; return; }
    i -= 2*BN;
    if (i < 128*144) {
        long o = i / 144, k = i % 144;
        g_pool[F_W2P + i] = (k < 132) ? round_tf32(c2W0[o*132 + k]) : 0.f;
        return;
    }
    i -= 128*144;
    if (i < 2*CC*CC) { g_pool[F_WC2 + i] = round_tf32(c2W[i]); return; }
    i -= 2*CC*CC;
    if (i < 256*272) { g_pool[F_WC10 + i] = round_tf32(c1W0[i]); return; }
    i -= 256*272;
    if (i < 2*256*256) { g_pool[F_WC1 + i] = round_tf32(c1W[i]); return; }
    i -= 2*256*256;
    if (i < 256*256) { g_pool[F_WM1 + i] = round_tf32(m1W[i]); return; }
    i -= 256*256;
    if (i < 256*256) { g_pool[F_WM2 + i] = round_tf32(m2W[i]); }
}

// both clouds: [B,C,N] -> [B,N,C] plus |.|^2 and |.|
__global__ void k_transpose_norm(const float* __restrict__ descS, const float* __restrict__ descD,
                                 float* __restrict__ dmatAll, float* __restrict__ nsqAll,
                                 float* __restrict__ nrmAll) {
    int cloud = blockIdx.y;
    const float* desc = cloud ? descD : descS;
    float* dmat = dmatAll + (long)cloud*BN*CC;
    float* nsq  = nsqAll  + cloud*BN;
    float* nrm  = nrmAll  + cloud*BN;
    int bn = blockIdx.x; int b = bn >> 11; int n = bn & (NN - 1);
    int c = threadIdx.x;
    float v = desc[((long)b*CC + c)*NN + n];
    dmat[(long)bn*CC + c] = v;
    float s = v * v;
    #pragma unroll
    for (int o = 16; o > 0; o >>= 1) s += __shfl_down_sync(0xffffffffu, s, o);
    __shared__ float ps[4];
    if ((c & 31) == 0) ps[c >> 5] = s;
    __syncthreads();
    if (c == 0) { float t = ps[0]+ps[1]+ps[2]+ps[3]; nsq[bn] = t; nrm[bn] = sqrtf(t); }
}

__global__ void k_rownorm(const float* __restrict__ dmat, float* __restrict__ nrm) {
    int bn = blockIdx.x; int c = threadIdx.x;
    float v = dmat[(long)bn*CC + c];
    float s = v * v;
    #pragma unroll
    for (int o = 16; o > 0; o >>= 1) s += __shfl_down_sync(0xffffffffu, s, o);
    __shared__ float ps[4];
    if ((c & 31) == 0) ps[c >> 5] = s;
    __syncthreads();
    if (c == 0) nrm[bn] = sqrtf(ps[0]+ps[1]+ps[2]+ps[3]);
}

// ---------------- split-tf32 sim GEMM: 3-stage cp.async, reg-side hi/lo ----------
#define SGM 128
#define SGN 64
#define SLD 20
#define SCLD 68
#define SSTG ((SGM+SGN)*SLD)

__global__ __launch_bounds__(256, 3)
void k_gemm_sim(const float* __restrict__ A, const float* __restrict__ Bm,
                float* __restrict__ Cm,
                const float* __restrict__ nrmA, const float* __restrict__ nrmB,
                float* __restrict__ maxDS, float* __restrict__ maxSD) {
    const int b = blockIdx.z;
    A  += (long)b * NN * CC;
    Bm += (long)b * NN * CC;
    Cm += (long)b * NN * NN;

    __shared__ __align__(16) float smem[3 * SSTG];
    float* Csm = smem;
    __shared__ float rns[SGM], rnd[SGN], rm[SGM], cmx[SGN];

    const int tid = threadIdx.x;
    const int lane = tid & 31;
    const int g   = lane >> 2;
    const int tig = lane & 3;
    const int wid = tid >> 5;
    const int wm = wid & 3;
    const int wn = wid >> 2;
    const long rowBase = (long)blockIdx.y * SGM;
    const int colBase = blockIdx.x * SGN;

    if (tid < SGM) { rns[tid] = nrmA[b*NN + rowBase + tid]; rm[tid] = -3.4e38f; }
    if (tid < SGN) { rnd[tid] = nrmB[b*NN + colBase + tid]; cmx[tid] = -3.4e38f; }

    const int srow = tid >> 2;
    const int kq = (tid & 3) * 4;
    unsigned sbase;
    asm("{ .reg .u64 t; cvta.to.shared.u64 t, %1; cvt.u32.u64 %0, t; }"
        : "=r"(sbase) : "l"(smem));

    auto issue = [&](int kc) {
        int buf = kc % 3;
        int k0 = kc * 16;
        const float* ga0 = &A[(rowBase + srow) * CC + k0 + kq];
        const float* ga1 = &A[(rowBase + srow + 64) * CC + k0 + kq];
        const float* gb  = &Bm[(long)(colBase + srow) * CC + k0 + kq];
        unsigned base = sbase + (unsigned)(buf * SSTG * 4);
        unsigned da0 = base + (unsigned)((srow * SLD + kq) * 4);
        unsigned da1 = da0 + 64u * SLD * 4u;
        unsigned db  = base + (unsigned)((SGM * SLD + srow * SLD + kq) * 4);
        cp_async16(da0, ga0);
        cp_async16(da1, ga1);
        cp_async16(db, gb);
        cp_commit();
    };

    float acc[2][4][4];
    #pragma unroll
    for (int i = 0; i < 2; i++)
        #pragma unroll
        for (int j = 0; j < 4; j++)
            #pragma unroll
            for (int t = 0; t < 4; t++)
                acc[i][j][t] = 0.f;

    const int nk = CC / 16;
    issue(0);
    issue(1);

    for (int kc = 0; kc < nk; kc++) {
        cp_wait<1>();
        __syncthreads();
        if (kc + 2 < nk) issue(kc + 2);
        const float* As = smem + (kc % 3) * SSTG;
        const float* Bs = As + SGM * SLD;
        #pragma unroll
        for (int ks = 0; ks < 2; ks++) {
            const int kb = ks * 8;
            unsigned bh0[4], bh1[4], bl0[4], bl1[4];
            #pragma unroll
            for (int nj = 0; nj < 4; nj++) {
                int nb = wn * 32 + nj * 8 + g;
                float w0 = Bs[nb * SLD + kb + tig];
                float w1 = Bs[nb * SLD + kb + tig + 4];
                unsigned h0 = cvt_tf32(w0), h1 = cvt_tf32(w1);
                bh0[nj] = h0; bh1[nj] = h1;
                bl0[nj] = cvt_tf32(w0 - __uint_as_float(h0));
                bl1[nj] = cvt_tf32(w1 - __uint_as_float(h1));
            }
            #pragma unroll
            for (int mi = 0; mi < 2; mi++) {
                int ar = wm * 32 + mi * 16;
                float v0 = As[(ar + g    ) * SLD + kb + tig];
                float v1 = As[(ar + g + 8) * SLD + kb + tig];
                float v2 = As[(ar + g    ) * SLD + kb + tig + 4];
                float v3 = As[(ar + g + 8) * SLD + kb + tig + 4];
                unsigned ah0 = cvt_tf32(v0), ah1 = cvt_tf32(v1);
                unsigned ah2 = cvt_tf32(v2), ah3 = cvt_tf32(v3);
                unsigned al0 = cvt_tf32(v0 - __uint_as_float(ah0));
                unsigned al1 = cvt_tf32(v1 - __uint_as_float(ah1));
                unsigned al2 = cvt_tf32(v2 - __uint_as_float(ah2));
                unsigned al3 = cvt_tf32(v3 - __uint_as_float(ah3));
                #pragma unroll
                for (int nj = 0; nj < 4; nj++) {
                    asm volatile(
                        "mma.sync.aligned.m16n8k8.row.col.f32.tf32.tf32.f32 "
                        "{%0,%1,%2,%3}, {%4,%5,%6,%7}, {%8,%9}, {%0,%1,%2,%3};"
                        : "+f"(acc[mi][nj][0]), "+f"(acc[mi][nj][1]),
                          "+f"(acc[mi][nj][2]), "+f"(acc[mi][nj][3])
                        : "r"(ah0), "r"(ah1), "r"(ah2), "r"(ah3),
                          "r"(bh0[nj]), "r"(bh1[nj]));
                    asm volatile(
                        "mma.sync.aligned.m16n8k8.row.col.f32.tf32.tf32.f32 "
                        "{%0,%1,%2,%3}, {%4,%5,%6,%7}, {%8,%9}, {%0,%1,%2,%3};"
                        : "+f"(acc[mi][nj][0]), "+f"(acc[mi][nj][1]),
                          "+f"(acc[mi][nj][2]), "+f"(acc[mi][nj][3])
                        : "r"(ah0), "r"(ah1), "r"(ah2), "r"(ah3),
                          "r"(bl0[nj]), "r"(bl1[nj]));
                    asm volatile(
                        "mma.sync.aligned.m16n8k8.row.col.f32.tf32.tf32.f32 "
                        "{%0,%1,%2,%3}, {%4,%5,%6,%7}, {%8,%9}, {%0,%1,%2,%3};"
                        : "+f"(acc[mi][nj][0]), "+f"(acc[mi][nj][1]),
                          "+f"(acc[mi][nj][2]), "+f"(acc[mi][nj][3])
                        : "r"(al0), "r"(al1), "r"(al2), "r"(al3),
                          "r"(bh0[nj]), "r"(bh1[nj]));
                }
            }
        }
    }
    __syncthreads();

    #pragma unroll
    for (int mi = 0; mi < 2; mi++) {
        int r0r = wm * 32 + mi * 16 + g;
        #pragma unroll
        for (int nj = 0; nj < 4; nj++) {
            int c0 = wn * 32 + nj * 8 + 2 * tig;
            Csm[r0r * SCLD + c0]           = acc[mi][nj][0];
            Csm[r0r * SCLD + c0 + 1]       = acc[mi][nj][1];
            Csm[(r0r + 8) * SCLD + c0]     = acc[mi][nj][2];
            Csm[(r0r + 8) * SCLD + c0 + 1] = acc[mi][nj][3];
        }
    }
    __syncthreads();

    const int ccol = tid & 63;
    const int r0 = tid >> 6;
    const float nd = rnd[ccol];
    float colmax = -3.4e38f;
    #pragma unroll 8
    for (int it = 0; it < 32; it++) {
        int r = r0 + it * 4;
        float v = Csm[r * SCLD + ccol];
        Cm[(rowBase + r) * NN + colBase + ccol] = v;
        float csv = v / (nd * rns[r] + EPSF);
        colmax = fmaxf(colmax, csv);
        float wmx = csv;
        #pragma unroll
        for (int o = 16; o > 0; o >>= 1) wmx = fmaxf(wmx, __shfl_down_sync(0xffffffffu, wmx, o));
        if (lane == 0) atomicMaxF(&rm[r], wmx);
    }
    atomicMaxF(&cmx[ccol], colmax);
    __syncthreads();
    if (tid < SGM) atomicMaxF(&maxDS[b*NN + rowBase + tid], rm[tid]);
    else if (tid < SGM + SGN) atomicMaxF(&maxSD[b*NN + colBase + (tid - SGM)], cmx[tid - SGM]);
}

// ---------------- TF32 conv GEMM v4: 3-stage cp.async, pre-rounded B (and A when !aff) ----
#define TCM 128
#define TCN 64
#define ALD 20
#define CLD 68
#define TSTG ((TCM+TCN)*ALD)

__global__ __launch_bounds__(256, 3)
void k_gemm_tc(const float* __restrict__ A, const float* __restrict__ Bm,
               float* __restrict__ Cm, int P, int O, int Kd,
               const float* __restrict__ affS, const float* __restrict__ affQ,
               const float* __restrict__ gP, const float* __restrict__ bP, float invP,
               float* __restrict__ statS, float* __restrict__ statQ, int splitRows) {
    __shared__ __align__(16) float smem[3 * TSTG];
    float* Csm = smem;
    __shared__ float cs[TCN], cq[TCN];
    __shared__ float sSc[256], sSh[256];

    const int tid = threadIdx.x;
    const int lane = tid & 31;
    const int g   = lane >> 2;
    const int tig = lane & 3;
    const int wid = tid >> 5;
    const int wm = wid & 3;
    const int wn = wid >> 2;
    const int rowBase = blockIdx.y * TCM;
    const int colBase = blockIdx.x * TCN;
    const bool aff = (affS != nullptr);
    const bool stats = (statS != nullptr);
    const int cloudA = (splitRows > 0 && rowBase >= splitRows) ? 1 : 0;
    const int statOff = cloudA * O;

    if (aff && tid < Kd && tid < 256) {
        int so = cloudA * Kd + tid;
        float mu  = affS[so] * invP;
        float var = fmaxf(affQ[so] * invP - mu * mu, 0.f);
        float s   = gP[tid] * rsqrtf(var + BNEPS);
        sSc[tid] = s;
        sSh[tid] = bP[tid] - mu * s;
    }
    if (stats && tid < TCN) { cs[tid] = 0.f; cq[tid] = 0.f; }

    const int srow = tid >> 2;
    const int kq = (tid & 3) * 4;
    unsigned sbase;
    asm("{ .reg .u64 t; cvta.to.shared.u64 t, %1; cvt.u32.u64 %0, t; }"
        : "=r"(sbase) : "l"(smem));

    auto issue = [&](int kc) {
        int buf = kc % 3;
        int k0 = kc * 16;
        const float* ga0 = &A[(long)(rowBase + srow) * Kd + k0 + kq];
        const float* ga1 = &A[(long)(rowBase + srow + 64) * Kd + k0 + kq];
        const float* gb  = &Bm[(long)(colBase + srow) * Kd + k0 + kq];
        unsigned base = sbase + (unsigned)(buf * TSTG * 4);
        unsigned da0 = base + (unsigned)((srow * ALD + kq) * 4);
        unsigned da1 = da0 + 64u * ALD * 4u;
        unsigned db  = base + (unsigned)((TCM * ALD + srow * ALD + kq) * 4);
        cp_async16(da0, ga0);
        cp_async16(da1, ga1);
        cp_async16(db, gb);
        cp_commit();
    };

    float acc[2][4][4];
    #pragma unroll
    for (int i = 0; i < 2; i++)
        #pragma unroll
        for (int j = 0; j < 4; j++)
            #pragma unroll
            for (int t = 0; t < 4; t++)
                acc[i][j][t] = 0.f;

    const int nk = Kd / 16;
    issue(0);
    issue(1);

    for (int kc = 0; kc < nk; kc++) {
        cp_wait<1>();
        __syncthreads();
        if (kc + 2 < nk) issue(kc + 2);
        const float* As = smem + (kc % 3) * TSTG;
        const float* Bs = As + TCM * ALD;
        const int k0 = kc * 16;
        #pragma unroll
        for (int ks = 0; ks < 2; ks++) {
            const int kb = ks * 8;
            unsigned b0[4], b1[4];
            #pragma unroll
            for (int nj = 0; nj < 4; nj++) {
                int nb = wn * 32 + nj * 8 + g;
                b0[nj] = __float_as_uint(Bs[nb * ALD + kb + tig]);
                b1[nj] = __float_as_uint(Bs[nb * ALD + kb + tig + 4]);
            }
            float sc0 = 1.f, sh0 = 0.f, sc4 = 1.f, sh4 = 0.f;
            if (aff) {
                sc0 = sSc[k0 + kb + tig];     sh0 = sSh[k0 + kb + tig];
                sc4 = sSc[k0 + kb + tig + 4]; sh4 = sSh[k0 + kb + tig + 4];
            }
            #pragma unroll
            for (int mi = 0; mi < 2; mi++) {
                int ar = wm * 32 + mi * 16;
                float v0 = As[(ar + g    ) * ALD + kb + tig];
                float v1 = As[(ar + g + 8) * ALD + kb + tig];
                float v2 = As[(ar + g    ) * ALD + kb + tig + 4];
                float v3 = As[(ar + g + 8) * ALD + kb + tig + 4];
                unsigned a0, a1, a2, a3;
                if (aff) {
                    a0 = cvt_tf32(fmaxf(v0 * sc0 + sh0, 0.f));
                    a1 = cvt_tf32(fmaxf(v1 * sc0 + sh0, 0.f));
                    a2 = cvt_tf32(fmaxf(v2 * sc4 + sh4, 0.f));
                    a3 = cvt_tf32(fmaxf(v3 * sc4 + sh4, 0.f));
                } else {
                    a0 = __float_as_uint(v0);
                    a1 = __float_as_uint(v1);
                    a2 = __float_as_uint(v2);
                    a3 = __float_as_uint(v3);
                }
                #pragma unroll
                for (int nj = 0; nj < 4; nj++) {
                    asm volatile(
                        "mma.sync.aligned.m16n8k8.row.col.f32.tf32.tf32.f32 "
                        "{%0,%1,%2,%3}, {%4,%5,%6,%7}, {%8,%9}, {%0,%1,%2,%3};"
                        : "+f"(acc[mi][nj][0]), "+f"(acc[mi][nj][1]),
                          "+f"(acc[mi][nj][2]), "+f"(acc[mi][nj][3])
                        : "r"(a0), "r"(a1), "r"(a2), "r"(a3),
                          "r"(b0[nj]), "r"(b1[nj]));
                }
            }
        }
    }
    __syncthreads();

    #pragma unroll
    for (int mi = 0; mi < 2; mi++) {
        int r0r = wm * 32 + mi * 16 + g;
        #pragma unroll
        for (int nj = 0; nj < 4; nj++) {
            int c0 = wn * 32 + nj * 8 + 2 * tig;
            Csm[r0r * CLD + c0]           = acc[mi][nj][0];
            Csm[r0r * CLD + c0 + 1]       = acc[mi][nj][1];
            Csm[(r0r + 8) * CLD + c0]     = acc[mi][nj][2];
            Csm[(r0r + 8) * CLD + c0 + 1] = acc[mi][nj][3];
        }
    }
    __syncthreads();

    const int ccol = tid & 63;
    const int r0 = tid >> 6;
    float s = 0.f, q = 0.f;
    #pragma unroll 8
    for (int it = 0; it < 32; it++) {
        int r = r0 + it * 4;
        float v = Csm[r * CLD + ccol];
        Cm[(long)(rowBase + r) * O + colBase + ccol] = v;
        s += v; q += v * v;
    }
    if (stats) {
        atomicAdd(&cs[ccol], s);
        atomicAdd(&cq[ccol], q);
        __syncthreads();
        if (tid < TCN) {
            atomicAdd(&statS[statOff + colBase + tid], cs[tid]);
            atomicAdd(&statQ[statOff + colBase + tid], cq[tid]);
        }
    }
}

// top-16 smallest from shared d2[NN], 256 threads (proven round-14 version)
__device__ void select_topk(float* d2, int* outIdx) {
    __shared__ float rv[8];
    __shared__ int   ri[8];
    int tid = threadIdx.x, lane = tid & 31, w = tid >> 5;
    for (int kk = 0; kk < KK; kk++) {
        float best = 3.4e38f; int bi = 0;
        for (int m = tid; m < NN; m += 256) {
            float v = d2[m];
            if (v < best) { best = v; bi = m; }
        }
        #pragma unroll
        for (int o = 16; o > 0; o >>= 1) {
            float ov = __shfl_down_sync(0xffffffffu, best, o);
            int   oi = __shfl_down_sync(0xffffffffu, bi, o);
            if (ov < best || (ov == best && oi < bi)) { best = ov; bi = oi; }
        }
        if (lane == 0) { rv[w] = best; ri[w] = bi; }
        __syncthreads();
        if (tid == 0) {
            float bv = rv[0]; int bj = ri[0];
            #pragma unroll
            for (int i = 1; i < 8; i++)
                if (rv[i] < bv || (rv[i] == bv && ri[i] < bj)) { bv = rv[i]; bj = ri[i]; }
            outIdx[kk] = bj;
            d2[bj] = 3.4e38f;
        }
        __syncthreads();
    }
}

__global__ void k_knn_desc(const float* __restrict__ inner, const float* __restrict__ nsqS,
                           const float* __restrict__ nsqD, int* __restrict__ idxOut) {
    int n = blockIdx.x, b = blockIdx.y;
    __shared__ float d2[NN];
    const float* row = inner + (long)b*NN*NN + (long)n*NN;
    float q = nsqS[b*NN + n];
    for (int m = threadIdx.x; m < NN; m += 256) d2[m] = q + nsqD[b*NN + m] - 2.f * row[m];
    __syncthreads();
    select_topk(d2, idxOut + ((long)b*NN + n) * KK);
}

__global__ void k_knn_xyz(const float* __restrict__ xyzS, const float* __restrict__ xyzD,
                          int* __restrict__ idxAll) {
    int n = blockIdx.x, b = blockIdx.y, cloud = blockIdx.z;
    const float* xyz = cloud ? xyzD : xyzS;
    int* idxOut = idxAll + (long)cloud*PP;
    __shared__ float d2[NN];
    long base = (long)b * NN * 3;
    float qx = xyz[base + (long)n*3], qy = xyz[base + (long)n*3+1], qz = xyz[base + (long)n*3+2];
    float qq = qx*qx + qy*qy + qz*qz;
    for (int m = threadIdx.x; m < NN; m += 256) {
        float rx = xyz[base + (long)m*3], ry = xyz[base + (long)m*3+1], rz = xyz[base + (long)m*3+2];
        d2[m] = qq + rx*rx + ry*ry + rz*rz - 2.f*(qx*rx + qy*ry + qz*rz);
    }
    __syncthreads();
    select_topk(d2, idxOut + ((long)b*NN + n) * KK);
}

__global__ void k_simgather(const float* __restrict__ inner, const float* __restrict__ nrmS,
                            const float* __restrict__ nrmD, const float* __restrict__ maxDS,
                            const float* __restrict__ maxSD, const int* __restrict__ idx,
                            float* __restrict__ outSD, float* __restrict__ outDS) {
    int t = blockIdx.x * 256 + threadIdx.x;
    if (t >= PP) return;
    int b = t / (NN * KK);
    int n = (t / KK) & (NN - 1);
    int m = idx[t];
    float v  = inner[(long)b*NN*NN + (long)n*NN + m];
    float cs = v / (nrmD[b*NN + m] * nrmS[b*NN + n] + EPSF);
    outSD[t] = cs / (maxDS[b*NN + n] + EPSF);
    outDS[t] = cs / (maxSD[b*NN + m] + EPSF);
}

// both clouds: nbr conv input, tf32-ROUNDED (feeds non-affine GEMM)
__global__ void k_build_nbr_f(const float* __restrict__ xyzS, const float* __restrict__ xyzD,
                              const float* __restrict__ dmatAll, const int* __restrict__ idxAll,
                              float* __restrict__ f) {
    int p = blockIdx.x;
    int cloud = p >= PP;
    int pl = p - cloud * PP;
    const float* xyz = cloud ? xyzD : xyzS;
    const float* dmatC = dmatAll + (long)cloud*BN*CC;
    int n = (pl / KK) & (NN - 1);
    int b = pl / (NN * KK);
    int m = idxAll[p];
    const float* dr = dmatC + ((long)b*NN + m) * CC;
    float* fo = f + (long)p * 144;
    int tid = threadIdx.x;
    fo[tid] = round_tf32(dr[tid]);
    if (tid == 0) {
        long qb = ((long)b*NN + n) * 3, rb = ((long)b*NN + m) * 3;
        float rx = xyz[rb]-xyz[qb], ry = xyz[rb+1]-xyz[qb+1], rz = xyz[rb+2]-xyz[qb+2];
        fo[128] = round_tf32(rx); fo[129] = round_tf32(ry); fo[130] = round_tf32(rz);
        fo[131] = round_tf32(sqrtf(rx*rx+ry*ry+rz*rz));
        #pragma unroll
        for (int z = 132; z < 144; z++) fo[z] = 0.f;
    }
}

// both clouds: grid 2*BN, in-block affine from producer stats
__global__ void k_nbr_final(const float* __restrict__ yraw,
                            const float* __restrict__ affS, const float* __restrict__ affQ,
                            const float* __restrict__ gP, const float* __restrict__ bP, float invP,
                            const int* __restrict__ idxAll,
                            const float* __restrict__ dmatAll, float* __restrict__ outAll) {
    int gblk = blockIdx.x;
    int cloud = gblk >= BN;
    int bn = gblk - cloud * BN;
    const float* y = yraw + (long)cloud*PP*CC;
    const int* idx = idxAll + (long)cloud*PP;
    const float* dmat = dmatAll + (long)cloud*BN*CC;
    float* outN = outAll + (long)cloud*BN*CC;
    int tid = threadIdx.x;
    __shared__ float fe[KK][CC];
    __shared__ float mk[KK], wgt[KK];
    __shared__ int sid[KK];
    __shared__ float sSc[CC], sSh[CC];
    if (tid < CC) {
        int so = cloud * CC + tid;
        float mu  = affS[so] * invP;
        float var = fmaxf(affQ[so] * invP - mu * mu, 0.f);
        float s   = gP[tid] * rsqrtf(var + BNEPS);
        sSc[tid] = s;
        sSh[tid] = bP[tid] - mu * s;
    }
    if (tid < KK) sid[tid] = idx[(long)bn*KK + tid];
    __syncthreads();
    for (int t = tid; t < KK * CC; t += 256) {
        int k = t >> 7, c = t & 127;
        float v = y[((long)bn*KK + k) * CC + c];
        fe[k][c] = fmaxf(v * sSc[c] + sSh[c], 0.f);
    }
    __syncthreads();
    int w = tid >> 5, lane = tid & 31;
    for (int kk = w; kk < KK; kk += 8) {
        float mx = -3.4e38f;
        for (int c = lane; c < CC; c += 32) mx = fmaxf(mx, fe[kk][c]);
        #pragma unroll
        for (int o = 16; o > 0; o >>= 1) mx = fmaxf(mx, __shfl_down_sync(0xffffffffu, mx, o));
        if (lane == 0) mk[kk] = mx;
    }
    __syncthreads();
    if (tid == 0) {
        float m = -3.4e38f;
        for (int k = 0; k < KK; k++) m = fmaxf(m, mk[k]);
        float s = 0.f;
        for (int k = 0; k < KK; k++) { float e = expf(mk[k]-m); wgt[k] = e; s += e; }
        float r = 1.f / s;
        for (int k = 0; k < KK; k++) wgt[k] *= r;
    }
    __syncthreads();
    if (tid < CC) {
        int b = bn >> 11;
        float a = 0.f;
        #pragma unroll
        for (int k = 0; k < KK; k++) a += wgt[k] * dmat[((long)b*NN + sid[k]) * CC + tid];
        outN[(long)bn*CC + tid] = a;
    }
}

// main feats build (272 ch), tf32-ROUNDED (feeds non-affine GEMM)
__global__ void k_build_feats(const float* __restrict__ src_xyz, const float* __restrict__ dst_xyz,
                              const float* __restrict__ srcd, const float* __restrict__ dstd,
                              const float* __restrict__ srcw, const float* __restrict__ dstw,
                              const float* __restrict__ sdc, const float* __restrict__ dsc,
                              const float* __restrict__ sdn, const float* __restrict__ dsn,
                              const int* __restrict__ idx, float* __restrict__ feats) {
    int p = blockIdx.x;
    int n = (p / KK) & (NN - 1);
    int b = p / (NN * KK);
    int m = idx[p];
    float* fo = feats + (long)p * 272;
    int tid = threadIdx.x;
    fo[10 + tid]  = round_tf32(srcd[((long)b*NN + n) * CC + tid]);
    fo[138 + tid] = round_tf32(dstd[((long)b*NN + m) * CC + tid]);
    if (tid == 0) {
        long qb = ((long)b*NN + n) * 3, rb = ((long)b*NN + m) * 3;
        float sx = src_xyz[qb], sy = src_xyz[qb+1], sz = src_xyz[qb+2];
        float kx = dst_xyz[rb], ky = dst_xyz[rb+1], kz = dst_xyz[rb+2];
        float rx = kx-sx, ry = ky-sy, rz = kz-sz;
        fo[0]=round_tf32(rx); fo[1]=round_tf32(ry); fo[2]=round_tf32(rz);
        fo[3]=round_tf32(sqrtf(rx*rx+ry*ry+rz*rz));
        fo[4]=round_tf32(sx); fo[5]=round_tf32(sy); fo[6]=round_tf32(sz);
        fo[7]=round_tf32(kx); fo[8]=round_tf32(ky); fo[9]=round_tf32(kz);
        fo[266]=round_tf32(srcw[b*NN+n]); fo[267]=round_tf32(dstw[b*NN+m]);
        fo[268]=round_tf32(sdc[p]); fo[269]=round_tf32(dsc[p]);
        fo[270]=round_tf32(sdn[p]); fo[271]=round_tf32(dsn[p]);
    }
}

__global__ void k_attention(const float* __restrict__ yraw,
                            const float* __restrict__ affS, const float* __restrict__ affQ,
                            const float* __restrict__ gP, const float* __restrict__ bP, float invP,
                            const int* __restrict__ idx, const float* __restrict__ dst_xyz,
                            float* __restrict__ outC, float* __restrict__ att) {
    int bn = blockIdx.x, tid = threadIdx.x;
    __shared__ float fe[KK][256];
    __shared__ float mk[KK], wgt[KK];
    __shared__ int sid[KK];
    if (tid < KK) sid[tid] = idx[(long)bn*KK + tid];
    float mu  = affS[tid] * invP;
    float var = fmaxf(affQ[tid] * invP - mu * mu, 0.f);
    float s   = gP[tid] * rsqrtf(var + BNEPS);
    float h   = bP[tid] - mu * s;
    #pragma unroll
    for (int k = 0; k < KK; k++) {
        float v = yraw[((long)bn*KK + k) * 256 + tid];
        fe[k][tid] = fmaxf(v * s + h, 0.f);
    }
    __syncthreads();
    int w = tid >> 5, lane = tid & 31;
    for (int kk = w; kk < KK; kk += 8) {
        float mx = -3.4e38f;
        for (int c = lane; c < 256; c += 32) mx = fmaxf(mx, fe[kk][c]);
        #pragma unroll
        for (int o = 16; o > 0; o >>= 1) mx = fmaxf(mx, __shfl_down_sync(0xffffffffu, mx, o));
        if (lane == 0) mk[kk] = mx;
    }
    __syncthreads();
    if (tid == 0) {
        float m = -3.4e38f;
        for (int k = 0; k < KK; k++) m = fmaxf(m, mk[k]);
        float ssum = 0.f;
        for (int k = 0; k < KK; k++) { float e = expf(mk[k]-m); wgt[k] = e; ssum += e; }
        float r = 1.f / ssum;
        for (int k = 0; k < KK; k++) wgt[k] *= r;
    }
    __syncthreads();
    float a = 0.f;
    #pragma unroll
    for (int k = 0; k < KK; k++) a += wgt[k] * fe[k][tid];
    att[(long)bn * 256 + tid] = round_tf32(a);
    if (tid < 3) {
        int b = bn >> 11;
        float cg = 0.f;
        #pragma unroll
        for (int k = 0; k < KK; k++)
            cg += wgt[k] * dst_xyz[((long)b*NN + sid[k]) * 3 + tid];
        outC[(long)bn * 3 + tid] = cg;
    }
}

__global__ void k_mlp3(const float* __restrict__ yraw,
                       const float* __restrict__ affS, const float* __restrict__ affQ,
                       const float* __restrict__ gP, const float* __restrict__ bP, float invP,
                       const float* __restrict__ w3, const float* __restrict__ b3,
                       float* __restrict__ outw) {
    int bn = blockIdx.x, tid = threadIdx.x;
    float mu  = affS[tid] * invP;
    float var = fmaxf(affQ[tid] * invP - mu * mu, 0.f);
    float s   = gP[tid] * rsqrtf(var + BNEPS);
    float h   = bP[tid] - mu * s;
    float v = fmaxf(yraw[(long)bn*256 + tid] * s + h, 0.f) * w3[tid];
    #pragma unroll
    for (int o = 16; o > 0; o >>= 1) v += __shfl_down_sync(0xffffffffu, v, o);
    __shared__ float ps[8];
    if ((tid & 31) == 0) ps[tid >> 5] = v;
    __syncthreads();
    if (tid == 0) {
        float s2 = 0.f;
        #pragma unroll
        for (int i = 0; i < 8; i++) s2 += ps[i];
        outw[bn] = 1.f / (1.f + expf(-(s2 + b3[0])));
    }
}

extern "C" void kernel_launch(void* const* d_in, const int* in_sizes, int n_in,
                              void* d_out, int out_size) {
    const float* src_xyz  = (const float*)d_in[0];
    const float* src_desc = (const float*)d_in[1];
    const float* dst_xyz  = (const float*)d_in[2];
    const float* dst_desc = (const float*)d_in[3];
    const float* src_w    = (const float*)d_in[4];
    const float* dst_w    = (const float*)d_in[5];
    const float* c1_W0 = (const float*)d_in[6];
    const float* c1_W  = (const float*)d_in[7];
    const float* c1_g  = (const float*)d_in[8];
    const float* c1_b  = (const float*)d_in[9];
    const float* c2_W0 = (const float*)d_in[10];
    const float* c2_W  = (const float*)d_in[11];
    const float* c2_g  = (const float*)d_in[12];
    const float* c2_b  = (const float*)d_in[13];
    const float* m1_W  = (const float*)d_in[14];
    const float* m1_g  = (const float*)d_in[16];
    const float* m1_b  = (const float*)d_in[17];
    const float* m2_W  = (const float*)d_in[18];
    const float* m2_g  = (const float*)d_in[20];
    const float* m2_b  = (const float*)d_in[21];
    const float* m3_W  = (const float*)d_in[22];
    const float* m3_b  = (const float*)d_in[23];

    float* base = nullptr;
    cudaGetSymbolAddress((void**)&base, g_pool);
    float* srcd   = base + F_SRCD;
    float* dstd   = base + F_DSTD;
    float* nsqS   = base + F_NSQS;
    float* nsqD   = base + F_NSQD;
    float* nrmS   = base + F_NRMS;
    float* nrmD   = base + F_NRMD;
    float* maxDS  = base + F_MAXDS;
    float* maxSD  = base + F_MAXSD;
    float* maxD2  = base + F_MAXD2;
    float* maxS2  = base + F_MAXS2;
    float* nrm2S  = base + F_NRM2S;
    float* nrm2D  = base + F_NRM2D;
    float* sdc    = base + F_SDC;
    float* dsc    = base + F_DSC;
    float* sdn    = base + F_SDN;
    float* dsn    = base + F_DSN;
    float* stat0  = base + F_STATS;
    float* w2p    = base + F_W2P;
    float* wc2    = base + F_WC2;
    float* wc10   = base + F_WC10;
    float* wc1    = base + F_WC1;
    float* wm1    = base + F_WM1;
    float* wm2    = base + F_WM2;
    int*   idx    = (int*)(base + F_IDX);
    int*   sidx   = (int*)(base + F_SIDX);
    float* att    = base + F_ATT;
    float* mb1    = base + F_MB1;
    float* mb2    = base + F_MB2;
    float* srcnbr = base + F_SRCNBR;
    float* inner  = base + F_INNER;
    float* fbuf   = base + F_F;
    float* y0     = base + F_Y0;
    float* y1     = base + F_Y1;
    float* outC   = (float*)d_out;
    float* outW   = (float*)d_out + (long)BB*NN*3;

    auto slot = [&](int i) { return stat0 + (long)i * 1024; };
    const float invPP = 1.f / (float)PP;
    const float invBN = 1.f / (float)BN;

    // ONE setup launch: stat zero + both rounds' max fills + all weight rounding
    k_setup<<<(SETUP_N + 255) / 256, 256>>>(c2_W0, c2_W, c1_W0, c1_W, m1_W, m2_W);

    // A: transpose + norms
    k_transpose_norm<<<dim3(BN, 2), 128>>>(src_desc, dst_desc, srcd, nsqS, nrmS);

    // inner = src . dst with fused cosine maxes
    k_gemm_sim<<<dim3(NN/SGN, NN/SGM, 2), 256>>>(srcd, dstd, inner, nrmS, nrmD, maxDS, maxSD);
    k_knn_desc<<<dim3(NN, BB), 256>>>(inner, nsqS, nsqD, idx);
    k_simgather<<<PP/256, 256>>>(inner, nrmS, nrmD, maxDS, maxSD, idx, sdc, dsc);

    // B: neighborhood descriptors — both clouds batched
    k_knn_xyz<<<dim3(NN, BB, 2), 256>>>(src_xyz, dst_xyz, sidx);
    k_build_nbr_f<<<2*PP, 128>>>(src_xyz, dst_xyz, srcd, sidx, fbuf);
    k_gemm_tc<<<dim3(CC/TCN, (2*PP)/TCM), 256>>>(fbuf, w2p, y0, 2*PP, CC, 144,
        nullptr, nullptr, nullptr, nullptr, 0.f, slot(0), slot(0)+512, PP);
    k_gemm_tc<<<dim3(CC/TCN, (2*PP)/TCM), 256>>>(y0, wc2, y1, 2*PP, CC, CC,
        slot(0), slot(0)+512, c2_g, c2_b, invPP, slot(1), slot(1)+512, PP);
    k_gemm_tc<<<dim3(CC/TCN, (2*PP)/TCM), 256>>>(y1, wc2 + CC*CC, y0, 2*PP, CC, CC,
        slot(1), slot(1)+512, c2_g + CC, c2_b + CC, invPP, slot(2), slot(2)+512, PP);
    k_nbr_final<<<2*BN, 256>>>(y0, slot(2), slot(2)+512, c2_g + 2*CC, c2_b + 2*CC, invPP,
                               sidx, srcd, srcnbr);

    // nbr cosine sims (separate max buffers; fill already done in setup)
    k_rownorm<<<2*BN, 128>>>(srcnbr, nrm2S);
    k_gemm_sim<<<dim3(NN/SGN, NN/SGM, 2), 256>>>(srcnbr, srcnbr + (long)BN*CC, inner,
                                                 nrm2S, nrm2D, maxD2, maxS2);
    k_simgather<<<PP/256, 256>>>(inner, nrm2S, nrm2D, maxD2, maxS2, idx, sdn, dsn);

    // C: main feature conv + attention
    k_build_feats<<<PP, 128>>>(src_xyz, dst_xyz, srcd, dstd, src_w, dst_w,
                               sdc, dsc, sdn, dsn, idx, fbuf);
    k_gemm_tc<<<dim3(256/TCN, PP/TCM), 256>>>(fbuf, wc10, y0, PP, 256, 272,
        nullptr, nullptr, nullptr, nullptr, 0.f, slot(3), slot(3)+512, 0);
    k_gemm_tc<<<dim3(256/TCN, PP/TCM), 256>>>(y0, wc1, y1, PP, 256, 256,
        slot(3), slot(3)+512, c1_g, c1_b, invPP, slot(4), slot(4)+512, 0);
    k_gemm_tc<<<dim3(256/TCN, PP/TCM), 256>>>(y1, wc1 + 256*256, y0, PP, 256, 256,
        slot(4), slot(4)+512, c1_g + 256, c1_b + 256, invPP, slot(5), slot(5)+512, 0);
    k_attention<<<BN, 256>>>(y0, slot(5), slot(5)+512, c1_g + 512, c1_b + 512, invPP,
                             idx, dst_xyz, outC, att);

    // D: MLP head
    k_gemm_tc<<<dim3(256/TCN, BN/TCM), 256>>>(att, wm1, mb1, BN, 256, 256,
        nullptr, nullptr, nullptr, nullptr, 0.f, slot(6), slot(6)+512, 0);
    k_gemm_tc<<<dim3(256/TCN, BN/TCM), 256>>>(mb1, wm2, mb2, BN, 256, 256,
        slot(6), slot(6)+512, m1_g, m1_b, invBN, slot(7), slot(7)+512, 0);
    k_mlp3<<<BN, 256>>>(mb2, slot(7), slot(7)+512, m2_g, m2_b, invBN, m3_W, m3_b, outW);
}

// round 17
// speedup vs baseline: 1.0308x; 1.0042x over previous
#include <cuda_runtime.h>
#include <mma.h>
#include <math.h>
#include <float.h>

using namespace nvcuda;

#define BB 2
#define NN 2048
#define CC 128
#define KK 16
#define BN (BB*NN)
#define PP (BB*NN*KK)
#define EPSF 1e-6f
#define BNEPS 1e-5f

// ---------------- scratch pool ----------------
constexpr long F_SRCD   = 0;
constexpr long F_DSTD   = F_SRCD   + (long)BN*CC;
constexpr long F_NSQS   = F_DSTD   + (long)BN*CC;
constexpr long F_NSQD   = F_NSQS   + BN;
constexpr long F_NRMS   = F_NSQD   + BN;
constexpr long F_NRMD   = F_NRMS   + BN;
constexpr long F_MAXDS  = F_NRMD   + BN;
constexpr long F_MAXSD  = F_MAXDS  + BN;
constexpr long F_MAXD2  = F_MAXSD  + BN;   // round-2 sim maxes (own buffers: fill folds into setup)
constexpr long F_MAXS2  = F_MAXD2  + BN;
constexpr long F_NRM2S  = F_MAXS2  + BN;
constexpr long F_NRM2D  = F_NRM2S  + BN;
constexpr long F_SDC    = F_NRM2D  + BN;
constexpr long F_DSC    = F_SDC    + PP;
constexpr long F_SDN    = F_DSC    + PP;
constexpr long F_DSN    = F_SDN    + PP;
constexpr long F_STATS  = F_DSN    + PP;            // 8 slots x 1024 (S at +0, Q at +512)
constexpr long F_W2P    = F_STATS  + 8*1024;        // padded+rounded c2_W0 [128][144]
constexpr long F_WC2    = F_W2P    + 128*144;       // rounded c2_W (2 x 128x128)
constexpr long F_WC10   = F_WC2    + 2*CC*CC;       // rounded c1_W0 (256x272)
constexpr long F_WC1    = F_WC10   + 256*272;       // rounded c1_W (2 x 256x256)
constexpr long F_WM1    = F_WC1    + 2*256*256;     // rounded m1_W
constexpr long F_WM2    = F_WM1    + 256*256;       // rounded m2_W
constexpr long F_IDX    = F_WM2    + 256*256;       // int
constexpr long F_SIDX   = F_IDX    + PP;
constexpr long F_DIDX   = F_SIDX   + PP;
constexpr long F_ATT    = F_DIDX   + PP;
constexpr long F_MB1    = F_ATT    + (long)BN*256;
constexpr long F_MB2    = F_MB1    + (long)BN*256;
constexpr long F_SRCNBR = F_MB2    + (long)BN*256;
constexpr long F_DSTNBR = F_SRCNBR + (long)BN*CC;
constexpr long F_INNER  = F_DSTNBR + (long)BN*CC;
constexpr long F_F      = F_INNER  + (long)BB*NN*NN;
constexpr long F_FSZ    = (long)2*PP*144;           // max(PP*272, 2PP*144)
constexpr long F_Y0     = F_F      + F_FSZ;
constexpr long F_Y1     = F_Y0     + (long)PP*256;
constexpr long F_END    = F_Y1     + (long)PP*256;

__device__ __align__(128) float g_pool[F_END];

__device__ __forceinline__ void atomicMaxF(float* a, float v) {
    if (!(v < 0.f)) atomicMax((int*)a, __float_as_int(v));
    else            atomicMin((unsigned int*)a, __float_as_uint(v));
}

__device__ __forceinline__ unsigned cvt_tf32(float x) {
    unsigned u;
    asm("cvt.rn.tf32.f32 %0, %1;" : "=r"(u) : "f"(x));
    return u;
}
__device__ __forceinline__ float round_tf32(float x) {
    return __uint_as_float(cvt_tf32(x));
}

__device__ __forceinline__ void cp_async16(unsigned saddr, const void* gptr) {
    asm volatile("cp.async.ca.shared.global [%0], [%1], 16;" :: "r"(saddr), "l"(gptr));
}
__device__ __forceinline__ void cp_commit() { asm volatile("cp.async.commit_group;"); }
template<int N> __device__ __forceinline__ void cp_wait() {
    asm volatile("cp.async.wait_group %0;" :: "n"(N));
}

// ---------------- single setup kernel: stat zero, max fills (both rounds), weight rounding ----
#define SETUP_N (8192 + 2*BN + 2*BN + 128*144 + 2*CC*CC + 256*272 + 2*256*256 + 256*256 + 256*256)

__global__ void k_setup(const float* __restrict__ c2W0, const float* __restrict__ c2W,
                        const float* __restrict__ c1W0, const float* __restrict__ c1W,
                        const float* __restrict__ m1W, const float* __restrict__ m2W) {
    long i = (long)blockIdx.x * 256 + threadIdx.x;
    if (i < 8192) { g_pool[F_STATS + i] = 0.f; return; }
    i -= 8192;
    if (i < 2*BN) { g_pool[F_MAXDS + i] = -3.4e38f; return; }
    i -= 2*BN;
    if (i < 2*BN) { g_pool[F_MAXD2 + i] = -3.4e38f; return; }
    i -= 2*BN;
    if (i < 128*144) {
        long o = i / 144, k = i % 144;
        g_pool[F_W2P + i] = (k < 132) ? round_tf32(c2W0[o*132 + k]) : 0.f;
        return;
    }
    i -= 128*144;
    if (i < 2*CC*CC) { g_pool[F_WC2 + i] = round_tf32(c2W[i]); return; }
    i -= 2*CC*CC;
    if (i < 256*272) { g_pool[F_WC10 + i] = round_tf32(c1W0[i]); return; }
    i -= 256*272;
    if (i < 2*256*256) { g_pool[F_WC1 + i] = round_tf32(c1W[i]); return; }
    i -= 2*256*256;
    if (i < 256*256) { g_pool[F_WM1 + i] = round_tf32(m1W[i]); return; }
    i -= 256*256;
    if (i < 256*256) { g_pool[F_WM2 + i] = round_tf32(m2W[i]); }
}

// both clouds: [B,C,N] -> [B,N,C] plus |.|^2 and |.|
__global__ void k_transpose_norm(const float* __restrict__ descS, const float* __restrict__ descD,
                                 float* __restrict__ dmatAll, float* __restrict__ nsqAll,
                                 float* __restrict__ nrmAll) {
    int cloud = blockIdx.y;
    const float* desc = cloud ? descD : descS;
    float* dmat = dmatAll + (long)cloud*BN*CC;
    float* nsq  = nsqAll  + cloud*BN;
    float* nrm  = nrmAll  + cloud*BN;
    int bn = blockIdx.x; int b = bn >> 11; int n = bn & (NN - 1);
    int c = threadIdx.x;
    float v = desc[((long)b*CC + c)*NN + n];
    dmat[(long)bn*CC + c] = v;
    float s = v * v;
    #pragma unroll
    for (int o = 16; o > 0; o >>= 1) s += __shfl_down_sync(0xffffffffu, s, o);
    __shared__ float ps[4];
    if ((c & 31) == 0) ps[c >> 5] = s;
    __syncthreads();
    if (c == 0) { float t = ps[0]+ps[1]+ps[2]+ps[3]; nsq[bn] = t; nrm[bn] = sqrtf(t); }
}

__global__ void k_rownorm(const float* __restrict__ dmat, float* __restrict__ nrm) {
    int bn = blockIdx.x; int c = threadIdx.x;
    float v = dmat[(long)bn*CC + c];
    float s = v * v;
    #pragma unroll
    for (int o = 16; o > 0; o >>= 1) s += __shfl_down_sync(0xffffffffu, s, o);
    __shared__ float ps[4];
    if ((c & 31) == 0) ps[c >> 5] = s;
    __syncthreads();
    if (c == 0) nrm[bn] = sqrtf(ps[0]+ps[1]+ps[2]+ps[3]);
}

// ---------------- split-tf32 sim GEMM: 3-stage cp.async, reg-side hi/lo ----------
#define SGM 128
#define SGN 64
#define SLD 20
#define SCLD 68
#define SSTG ((SGM+SGN)*SLD)

__global__ __launch_bounds__(256, 3)
void k_gemm_sim(const float* __restrict__ A, const float* __restrict__ Bm,
                float* __restrict__ Cm,
                const float* __restrict__ nrmA, const float* __restrict__ nrmB,
                float* __restrict__ maxDS, float* __restrict__ maxSD) {
    const int b = blockIdx.z;
    A  += (long)b * NN * CC;
    Bm += (long)b * NN * CC;
    Cm += (long)b * NN * NN;

    __shared__ __align__(16) float smem[3 * SSTG];
    float* Csm = smem;
    __shared__ float rns[SGM], rnd[SGN], rm[SGM], cmx[SGN];

    const int tid = threadIdx.x;
    const int lane = tid & 31;
    const int g   = lane >> 2;
    const int tig = lane & 3;
    const int wid = tid >> 5;
    const int wm = wid & 3;
    const int wn = wid >> 2;
    const long rowBase = (long)blockIdx.y * SGM;
    const int colBase = blockIdx.x * SGN;

    if (tid < SGM) { rns[tid] = nrmA[b*NN + rowBase + tid]; rm[tid] = -3.4e38f; }
    if (tid < SGN) { rnd[tid] = nrmB[b*NN + colBase + tid]; cmx[tid] = -3.4e38f; }

    const int srow = tid >> 2;
    const int kq = (tid & 3) * 4;
    unsigned sbase;
    asm("{ .reg .u64 t; cvta.to.shared.u64 t, %1; cvt.u32.u64 %0, t; }"
        : "=r"(sbase) : "l"(smem));

    auto issue = [&](int kc) {
        int buf = kc % 3;
        int k0 = kc * 16;
        const float* ga0 = &A[(rowBase + srow) * CC + k0 + kq];
        const float* ga1 = &A[(rowBase + srow + 64) * CC + k0 + kq];
        const float* gb  = &Bm[(long)(colBase + srow) * CC + k0 + kq];
        unsigned base = sbase + (unsigned)(buf * SSTG * 4);
        unsigned da0 = base + (unsigned)((srow * SLD + kq) * 4);
        unsigned da1 = da0 + 64u * SLD * 4u;
        unsigned db  = base + (unsigned)((SGM * SLD + srow * SLD + kq) * 4);
        cp_async16(da0, ga0);
        cp_async16(da1, ga1);
        cp_async16(db, gb);
        cp_commit();
    };

    float acc[2][4][4];
    #pragma unroll
    for (int i = 0; i < 2; i++)
        #pragma unroll
        for (int j = 0; j < 4; j++)
            #pragma unroll
            for (int t = 0; t < 4; t++)
                acc[i][j][t] = 0.f;

    const int nk = CC / 16;
    issue(0);
    issue(1);

    for (int kc = 0; kc < nk; kc++) {
        cp_wait<1>();
        __syncthreads();
        if (kc + 2 < nk) issue(kc + 2);
        const float* As = smem + (kc % 3) * SSTG;
        const float* Bs = As + SGM * SLD;
        #pragma unroll
        for (int ks = 0; ks < 2; ks++) {
            const int kb = ks * 8;
            unsigned bh0[4], bh1[4], bl0[4], bl1[4];
            #pragma unroll
            for (int nj = 0; nj < 4; nj++) {
                int nb = wn * 32 + nj * 8 + g;
                float w0 = Bs[nb * SLD + kb + tig];
                float w1 = Bs[nb * SLD + kb + tig + 4];
                unsigned h0 = cvt_tf32(w0), h1 = cvt_tf32(w1);
                bh0[nj] = h0; bh1[nj] = h1;
                bl0[nj] = cvt_tf32(w0 - __uint_as_float(h0));
                bl1[nj] = cvt_tf32(w1 - __uint_as_float(h1));
            }
            #pragma unroll
            for (int mi = 0; mi < 2; mi++) {
                int ar = wm * 32 + mi * 16;
                float v0 = As[(ar + g    ) * SLD + kb + tig];
                float v1 = As[(ar + g + 8) * SLD + kb + tig];
                float v2 = As[(ar + g    ) * SLD + kb + tig + 4];
                float v3 = As[(ar + g + 8) * SLD + kb + tig + 4];
                unsigned ah0 = cvt_tf32(v0), ah1 = cvt_tf32(v1);
                unsigned ah2 = cvt_tf32(v2), ah3 = cvt_tf32(v3);
                unsigned al0 = cvt_tf32(v0 - __uint_as_float(ah0));
                unsigned al1 = cvt_tf32(v1 - __uint_as_float(ah1));
                unsigned al2 = cvt_tf32(v2 - __uint_as_float(ah2));
                unsigned al3 = cvt_tf32(v3 - __uint_as_float(ah3));
                #pragma unroll
                for (int nj = 0; nj < 4; nj++) {
                    asm volatile(
                        "mma.sync.aligned.m16n8k8.row.col.f32.tf32.tf32.f32 "
                        "{%0,%1,%2,%3}, {%4,%5,%6,%7}, {%8,%9}, {%0,%1,%2,%3};"
                        : "+f"(acc[mi][nj][0]), "+f"(acc[mi][nj][1]),
                          "+f"(acc[mi][nj][2]), "+f"(acc[mi][nj][3])
                        : "r"(ah0), "r"(ah1), "r"(ah2), "r"(ah3),
                          "r"(bh0[nj]), "r"(bh1[nj]));
                    asm volatile(
                        "mma.sync.aligned.m16n8k8.row.col.f32.tf32.tf32.f32 "
                        "{%0,%1,%2,%3}, {%4,%5,%6,%7}, {%8,%9}, {%0,%1,%2,%3};"
                        : "+f"(acc[mi][nj][0]), "+f"(acc[mi][nj][1]),
                          "+f"(acc[mi][nj][2]), "+f"(acc[mi][nj][3])
                        : "r"(ah0), "r"(ah1), "r"(ah2), "r"(ah3),
                          "r"(bl0[nj]), "r"(bl1[nj]));
                    asm volatile(
                        "mma.sync.aligned.m16n8k8.row.col.f32.tf32.tf32.f32 "
                        "{%0,%1,%2,%3}, {%4,%5,%6,%7}, {%8,%9}, {%0,%1,%2,%3};"
                        : "+f"(acc[mi][nj][0]), "+f"(acc[mi][nj][1]),
                          "+f"(acc[mi][nj][2]), "+f"(acc[mi][nj][3])
                        : "r"(al0), "r"(al1), "r"(al2), "r"(al3),
                          "r"(bh0[nj]), "r"(bh1[nj]));
                }
            }
        }
    }
    __syncthreads();

    #pragma unroll
    for (int mi = 0; mi < 2; mi++) {
        int r0r = wm * 32 + mi * 16 + g;
        #pragma unroll
        for (int nj = 0; nj < 4; nj++) {
            int c0 = wn * 32 + nj * 8 + 2 * tig;
            Csm[r0r * SCLD + c0]           = acc[mi][nj][0];
            Csm[r0r * SCLD + c0 + 1]       = acc[mi][nj][1];
            Csm[(r0r + 8) * SCLD + c0]     = acc[mi][nj][2];
            Csm[(r0r + 8) * SCLD + c0 + 1] = acc[mi][nj][3];
        }
    }
    __syncthreads();

    const int ccol = tid & 63;
    const int r0 = tid >> 6;
    const float nd = rnd[ccol];
    float colmax = -3.4e38f;
    #pragma unroll 8
    for (int it = 0; it < 32; it++) {
        int r = r0 + it * 4;
        float v = Csm[r * SCLD + ccol];
        Cm[(rowBase + r) * NN + colBase + ccol] = v;
        float csv = v / (nd * rns[r] + EPSF);
        colmax = fmaxf(colmax, csv);
        float wmx = csv;
        #pragma unroll
        for (int o = 16; o > 0; o >>= 1) wmx = fmaxf(wmx, __shfl_down_sync(0xffffffffu, wmx, o));
        if (lane == 0) atomicMaxF(&rm[r], wmx);
    }
    atomicMaxF(&cmx[ccol], colmax);
    __syncthreads();
    if (tid < SGM) atomicMaxF(&maxDS[b*NN + rowBase + tid], rm[tid]);
    else if (tid < SGM + SGN) atomicMaxF(&maxSD[b*NN + colBase + (tid - SGM)], cmx[tid - SGM]);
}

// ---------------- TF32 conv GEMM v4: 3-stage cp.async, pre-rounded B (and A when !aff) ----
#define TCM 128
#define TCN 64
#define ALD 20
#define CLD 68
#define TSTG ((TCM+TCN)*ALD)

__global__ __launch_bounds__(256, 3)
void k_gemm_tc(const float* __restrict__ A, const float* __restrict__ Bm,
               float* __restrict__ Cm, int P, int O, int Kd,
               const float* __restrict__ affS, const float* __restrict__ affQ,
               const float* __restrict__ gP, const float* __restrict__ bP, float invP,
               float* __restrict__ statS, float* __restrict__ statQ, int splitRows) {
    __shared__ __align__(16) float smem[3 * TSTG];
    float* Csm = smem;
    __shared__ float cs[TCN], cq[TCN];
    __shared__ float sSc[256], sSh[256];

    const int tid = threadIdx.x;
    const int lane = tid & 31;
    const int g   = lane >> 2;
    const int tig = lane & 3;
    const int wid = tid >> 5;
    const int wm = wid & 3;
    const int wn = wid >> 2;
    const int rowBase = blockIdx.y * TCM;
    const int colBase = blockIdx.x * TCN;
    const bool aff = (affS != nullptr);
    const bool stats = (statS != nullptr);
    const int cloudA = (splitRows > 0 && rowBase >= splitRows) ? 1 : 0;
    const int statOff = cloudA * O;

    if (aff && tid < Kd && tid < 256) {
        int so = cloudA * Kd + tid;
        float mu  = affS[so] * invP;
        float var = fmaxf(affQ[so] * invP - mu * mu, 0.f);
        float s   = gP[tid] * rsqrtf(var + BNEPS);
        sSc[tid] = s;
        sSh[tid] = bP[tid] - mu * s;
    }
    if (stats && tid < TCN) { cs[tid] = 0.f; cq[tid] = 0.f; }

    const int srow = tid >> 2;
    const int kq = (tid & 3) * 4;
    unsigned sbase;
    asm("{ .reg .u64 t; cvta.to.shared.u64 t, %1; cvt.u32.u64 %0, t; }"
        : "=r"(sbase) : "l"(smem));

    auto issue = [&](int kc) {
        int buf = kc % 3;
        int k0 = kc * 16;
        const float* ga0 = &A[(long)(rowBase + srow) * Kd + k0 + kq];
        const float* ga1 = &A[(long)(rowBase + srow + 64) * Kd + k0 + kq];
        const float* gb  = &Bm[(long)(colBase + srow) * Kd + k0 + kq];
        unsigned base = sbase + (unsigned)(buf * TSTG * 4);
        unsigned da0 = base + (unsigned)((srow * ALD + kq) * 4);
        unsigned da1 = da0 + 64u * ALD * 4u;
        unsigned db  = base + (unsigned)((TCM * ALD + srow * ALD + kq) * 4);
        cp_async16(da0, ga0);
        cp_async16(da1, ga1);
        cp_async16(db, gb);
        cp_commit();
    };

    float acc[2][4][4];
    #pragma unroll
    for (int i = 0; i < 2; i++)
        #pragma unroll
        for (int j = 0; j < 4; j++)
            #pragma unroll
            for (int t = 0; t < 4; t++)
                acc[i][j][t] = 0.f;

    const int nk = Kd / 16;
    issue(0);
    issue(1);

    for (int kc = 0; kc < nk; kc++) {
        cp_wait<1>();
        __syncthreads();
        if (kc + 2 < nk) issue(kc + 2);
        const float* As = smem + (kc % 3) * TSTG;
        const float* Bs = As + TCM * ALD;
        const int k0 = kc * 16;
        #pragma unroll
        for (int ks = 0; ks < 2; ks++) {
            const int kb = ks * 8;
            unsigned b0[4], b1[4];
            #pragma unroll
            for (int nj = 0; nj < 4; nj++) {
                int nb = wn * 32 + nj * 8 + g;
                b0[nj] = __float_as_uint(Bs[nb * ALD + kb + tig]);
                b1[nj] = __float_as_uint(Bs[nb * ALD + kb + tig + 4]);
            }
            float sc0 = 1.f, sh0 = 0.f, sc4 = 1.f, sh4 = 0.f;
            if (aff) {
                sc0 = sSc[k0 + kb + tig];     sh0 = sSh[k0 + kb + tig];
                sc4 = sSc[k0 + kb + tig + 4]; sh4 = sSh[k0 + kb + tig + 4];
            }
            #pragma unroll
            for (int mi = 0; mi < 2; mi++) {
                int ar = wm * 32 + mi * 16;
                float v0 = As[(ar + g    ) * ALD + kb + tig];
                float v1 = As[(ar + g + 8) * ALD + kb + tig];
                float v2 = As[(ar + g    ) * ALD + kb + tig + 4];
                float v3 = As[(ar + g + 8) * ALD + kb + tig + 4];
                unsigned a0, a1, a2, a3;
                if (aff) {
                    a0 = cvt_tf32(fmaxf(v0 * sc0 + sh0, 0.f));
                    a1 = cvt_tf32(fmaxf(v1 * sc0 + sh0, 0.f));
                    a2 = cvt_tf32(fmaxf(v2 * sc4 + sh4, 0.f));
                    a3 = cvt_tf32(fmaxf(v3 * sc4 + sh4, 0.f));
                } else {
                    a0 = __float_as_uint(v0);
                    a1 = __float_as_uint(v1);
                    a2 = __float_as_uint(v2);
                    a3 = __float_as_uint(v3);
                }
                #pragma unroll
                for (int nj = 0; nj < 4; nj++) {
                    asm volatile(
                        "mma.sync.aligned.m16n8k8.row.col.f32.tf32.tf32.f32 "
                        "{%0,%1,%2,%3}, {%4,%5,%6,%7}, {%8,%9}, {%0,%1,%2,%3};"
                        : "+f"(acc[mi][nj][0]), "+f"(acc[mi][nj][1]),
                          "+f"(acc[mi][nj][2]), "+f"(acc[mi][nj][3])
                        : "r"(a0), "r"(a1), "r"(a2), "r"(a3),
                          "r"(b0[nj]), "r"(b1[nj]));
                }
            }
        }
    }
    __syncthreads();

    #pragma unroll
    for (int mi = 0; mi < 2; mi++) {
        int r0r = wm * 32 + mi * 16 + g;
        #pragma unroll
        for (int nj = 0; nj < 4; nj++) {
            int c0 = wn * 32 + nj * 8 + 2 * tig;
            Csm[r0r * CLD + c0]           = acc[mi][nj][0];
            Csm[r0r * CLD + c0 + 1]       = acc[mi][nj][1];
            Csm[(r0r + 8) * CLD + c0]     = acc[mi][nj][2];
            Csm[(r0r + 8) * CLD + c0 + 1] = acc[mi][nj][3];
        }
    }
    __syncthreads();

    const int ccol = tid & 63;
    const int r0 = tid >> 6;
    float s = 0.f, q = 0.f;
    #pragma unroll 8
    for (int it = 0; it < 32; it++) {
        int r = r0 + it * 4;
        float v = Csm[r * CLD + ccol];
        Cm[(long)(rowBase + r) * O + colBase + ccol] = v;
        s += v; q += v * v;
    }
    if (stats) {
        atomicAdd(&cs[ccol], s);
        atomicAdd(&cq[ccol], q);
        __syncthreads();
        if (tid < TCN) {
            atomicAdd(&statS[statOff + colBase + tid], cs[tid]);
            atomicAdd(&statQ[statOff + colBase + tid], cq[tid]);
        }
    }
}

// top-16 smallest from shared d2[NN], 256 threads (proven round-14 version)
__device__ void select_topk(float* d2, int* outIdx) {
    __shared__ float rv[8];
    __shared__ int   ri[8];
    int tid = threadIdx.x, lane = tid & 31, w = tid >> 5;
    for (int kk = 0; kk < KK; kk++) {
        float best = 3.4e38f; int bi = 0;
        for (int m = tid; m < NN; m += 256) {
            float v = d2[m];
            if (v < best) { best = v; bi = m; }
        }
        #pragma unroll
        for (int o = 16; o > 0; o >>= 1) {
            float ov = __shfl_down_sync(0xffffffffu, best, o);
            int   oi = __shfl_down_sync(0xffffffffu, bi, o);
            if (ov < best || (ov == best && oi < bi)) { best = ov; bi = oi; }
        }
        if (lane == 0) { rv[w] = best; ri[w] = bi; }
        __syncthreads();
        if (tid == 0) {
            float bv = rv[0]; int bj = ri[0];
            #pragma unroll
            for (int i = 1; i < 8; i++)
                if (rv[i] < bv || (rv[i] == bv && ri[i] < bj)) { bv = rv[i]; bj = ri[i]; }
            outIdx[kk] = bj;
            d2[bj] = 3.4e38f;
        }
        __syncthreads();
    }
}

__global__ void k_knn_desc(const float* __restrict__ inner, const float* __restrict__ nsqS,
                           const float* __restrict__ nsqD, int* __restrict__ idxOut) {
    int n = blockIdx.x, b = blockIdx.y;
    __shared__ float d2[NN];
    const float* row = inner + (long)b*NN*NN + (long)n*NN;
    float q = nsqS[b*NN + n];
    for (int m = threadIdx.x; m < NN; m += 256) d2[m] = q + nsqD[b*NN + m] - 2.f * row[m];
    __syncthreads();
    select_topk(d2, idxOut + ((long)b*NN + n) * KK);
}

__global__ void k_knn_xyz(const float* __restrict__ xyzS, const float* __restrict__ xyzD,
                          int* __restrict__ idxAll) {
    int n = blockIdx.x, b = blockIdx.y, cloud = blockIdx.z;
    const float* xyz = cloud ? xyzD : xyzS;
    int* idxOut = idxAll + (long)cloud*PP;
    __shared__ float d2[NN];
    long base = (long)b * NN * 3;
    float qx = xyz[base + (long)n*3], qy = xyz[base + (long)n*3+1], qz = xyz[base + (long)n*3+2];
    float qq = qx*qx + qy*qy + qz*qz;
    for (int m = threadIdx.x; m < NN; m += 256) {
        float rx = xyz[base + (long)m*3], ry = xyz[base + (long)m*3+1], rz = xyz[base + (long)m*3+2];
        d2[m] = qq + rx*rx + ry*ry + rz*rz - 2.f*(qx*rx + qy*ry + qz*rz);
    }
    __syncthreads();
    select_topk(d2, idxOut + ((long)b*NN + n) * KK);
}

__global__ void k_simgather(const float* __restrict__ inner, const float* __restrict__ nrmS,
                            const float* __restrict__ nrmD, const float* __restrict__ maxDS,
                            const float* __restrict__ maxSD, const int* __restrict__ idx,
                            float* __restrict__ outSD, float* __restrict__ outDS) {
    int t = blockIdx.x * 256 + threadIdx.x;
    if (t >= PP) return;
    int b = t / (NN * KK);
    int n = (t / KK) & (NN - 1);
    int m = idx[t];
    float v  = inner[(long)b*NN*NN + (long)n*NN + m];
    float cs = v / (nrmD[b*NN + m] * nrmS[b*NN + n] + EPSF);
    outSD[t] = cs / (maxDS[b*NN + n] + EPSF);
    outDS[t] = cs / (maxSD[b*NN + m] + EPSF);
}

// both clouds: nbr conv input, tf32-ROUNDED (feeds non-affine GEMM)
__global__ void k_build_nbr_f(const float* __restrict__ xyzS, const float* __restrict__ xyzD,
                              const float* __restrict__ dmatAll, const int* __restrict__ idxAll,
                              float* __restrict__ f) {
    int p = blockIdx.x;
    int cloud = p >= PP;
    int pl = p - cloud * PP;
    const float* xyz = cloud ? xyzD : xyzS;
    const float* dmatC = dmatAll + (long)cloud*BN*CC;
    int n = (pl / KK) & (NN - 1);
    int b = pl / (NN * KK);
    int m = idxAll[p];
    const float* dr = dmatC + ((long)b*NN + m) * CC;
    float* fo = f + (long)p * 144;
    int tid = threadIdx.x;
    fo[tid] = round_tf32(dr[tid]);
    if (tid == 0) {
        long qb = ((long)b*NN + n) * 3, rb = ((long)b*NN + m) * 3;
        float rx = xyz[rb]-xyz[qb], ry = xyz[rb+1]-xyz[qb+1], rz = xyz[rb+2]-xyz[qb+2];
        fo[128] = round_tf32(rx); fo[129] = round_tf32(ry); fo[130] = round_tf32(rz);
        fo[131] = round_tf32(sqrtf(rx*rx+ry*ry+rz*rz));
        #pragma unroll
        for (int z = 132; z < 144; z++) fo[z] = 0.f;
    }
}

// both clouds: grid 2*BN, in-block affine from producer stats
__global__ void k_nbr_final(const float* __restrict__ yraw,
                            const float* __restrict__ affS, const float* __restrict__ affQ,
                            const float* __restrict__ gP, const float* __restrict__ bP, float invP,
                            const int* __restrict__ idxAll,
                            const float* __restrict__ dmatAll, float* __restrict__ outAll) {
    int gblk = blockIdx.x;
    int cloud = gblk >= BN;
    int bn = gblk - cloud * BN;
    const float* y = yraw + (long)cloud*PP*CC;
    const int* idx = idxAll + (long)cloud*PP;
    const float* dmat = dmatAll + (long)cloud*BN*CC;
    float* outN = outAll + (long)cloud*BN*CC;
    int tid = threadIdx.x;
    __shared__ float fe[KK][CC];
    __shared__ float mk[KK], wgt[KK];
    __shared__ int sid[KK];
    __shared__ float sSc[CC], sSh[CC];
    if (tid < CC) {
        int so = cloud * CC + tid;
        float mu  = affS[so] * invP;
        float var = fmaxf(affQ[so] * invP - mu * mu, 0.f);
        float s   = gP[tid] * rsqrtf(var + BNEPS);
        sSc[tid] = s;
        sSh[tid] = bP[tid] - mu * s;
    }
    if (tid < KK) sid[tid] = idx[(long)bn*KK + tid];
    __syncthreads();
    for (int t = tid; t < KK * CC; t += 256) {
        int k = t >> 7, c = t & 127;
        float v = y[((long)bn*KK + k) * CC + c];
        fe[k][c] = fmaxf(v * sSc[c] + sSh[c], 0.f);
    }
    __syncthreads();
    int w = tid >> 5, lane = tid & 31;
    for (int kk = w; kk < KK; kk += 8) {
        float mx = -3.4e38f;
        for (int c = lane; c < CC; c += 32) mx = fmaxf(mx, fe[kk][c]);
        #pragma unroll
        for (int o = 16; o > 0; o >>= 1) mx = fmaxf(mx, __shfl_down_sync(0xffffffffu, mx, o));
        if (lane == 0) mk[kk] = mx;
    }
    __syncthreads();
    if (tid == 0) {
        float m = -3.4e38f;
        for (int k = 0; k < KK; k++) m = fmaxf(m, mk[k]);
        float s = 0.f;
        for (int k = 0; k < KK; k++) { float e = expf(mk[k]-m); wgt[k] = e; s += e; }
        float r = 1.f / s;
        for (int k = 0; k < KK; k++) wgt[k] *= r;
    }
    __syncthreads();
    if (tid < CC) {
        int b = bn >> 11;
        float a = 0.f;
        #pragma unroll
        for (int k = 0; k < KK; k++) a += wgt[k] * dmat[((long)b*NN + sid[k]) * CC + tid];
        outN[(long)bn*CC + tid] = a;
    }
}

// main feats build (272 ch), tf32-ROUNDED (feeds non-affine GEMM)
__global__ void k_build_feats(const float* __restrict__ src_xyz, const float* __restrict__ dst_xyz,
                              const float* __restrict__ srcd, const float* __restrict__ dstd,
                              const float* __restrict__ srcw, const float* __restrict__ dstw,
                              const float* __restrict__ sdc, const float* __restrict__ dsc,
                              const float* __restrict__ sdn, const float* __restrict__ dsn,
                              const int* __restrict__ idx, float* __restrict__ feats) {
    int p = blockIdx.x;
    int n = (p / KK) & (NN - 1);
    int b = p / (NN * KK);
    int m = idx[p];
    float* fo = feats + (long)p * 272;
    int tid = threadIdx.x;
    fo[10 + tid]  = round_tf32(srcd[((long)b*NN + n) * CC + tid]);
    fo[138 + tid] = round_tf32(dstd[((long)b*NN + m) * CC + tid]);
    if (tid == 0) {
        long qb = ((long)b*NN + n) * 3, rb = ((long)b*NN + m) * 3;
        float sx = src_xyz[qb], sy = src_xyz[qb+1], sz = src_xyz[qb+2];
        float kx = dst_xyz[rb], ky = dst_xyz[rb+1], kz = dst_xyz[rb+2];
        float rx = kx-sx, ry = ky-sy, rz = kz-sz;
        fo[0]=round_tf32(rx); fo[1]=round_tf32(ry); fo[2]=round_tf32(rz);
        fo[3]=round_tf32(sqrtf(rx*rx+ry*ry+rz*rz));
        fo[4]=round_tf32(sx); fo[5]=round_tf32(sy); fo[6]=round_tf32(sz);
        fo[7]=round_tf32(kx); fo[8]=round_tf32(ky); fo[9]=round_tf32(kz);
        fo[266]=round_tf32(srcw[b*NN+n]); fo[267]=round_tf32(dstw[b*NN+m]);
        fo[268]=round_tf32(sdc[p]); fo[269]=round_tf32(dsc[p]);
        fo[270]=round_tf32(sdn[p]); fo[271]=round_tf32(dsn[p]);
    }
}

__global__ void k_attention(const float* __restrict__ yraw,
                            const float* __restrict__ affS, const float* __restrict__ affQ,
                            const float* __restrict__ gP, const float* __restrict__ bP, float invP,
                            const int* __restrict__ idx, const float* __restrict__ dst_xyz,
                            float* __restrict__ outC, float* __restrict__ att) {
    int bn = blockIdx.x, tid = threadIdx.x;
    __shared__ float fe[KK][256];
    __shared__ float mk[KK], wgt[KK];
    __shared__ int sid[KK];
    if (tid < KK) sid[tid] = idx[(long)bn*KK + tid];
    float mu  = affS[tid] * invP;
    float var = fmaxf(affQ[tid] * invP - mu * mu, 0.f);
    float s   = gP[tid] * rsqrtf(var + BNEPS);
    float h   = bP[tid] - mu * s;
    #pragma unroll
    for (int k = 0; k < KK; k++) {
        float v = yraw[((long)bn*KK + k) * 256 + tid];
        fe[k][tid] = fmaxf(v * s + h, 0.f);
    }
    __syncthreads();
    int w = tid >> 5, lane = tid & 31;
    for (int kk = w; kk < KK; kk += 8) {
        float mx = -3.4e38f;
        for (int c = lane; c < 256; c += 32) mx = fmaxf(mx, fe[kk][c]);
        #pragma unroll
        for (int o = 16; o > 0; o >>= 1) mx = fmaxf(mx, __shfl_down_sync(0xffffffffu, mx, o));
        if (lane == 0) mk[kk] = mx;
    }
    __syncthreads();
    if (tid == 0) {
        float m = -3.4e38f;
        for (int k = 0; k < KK; k++) m = fmaxf(m, mk[k]);
        float ssum = 0.f;
        for (int k = 0; k < KK; k++) { float e = expf(mk[k]-m); wgt[k] = e; ssum += e; }
        float r = 1.f / ssum;
        for (int k = 0; k < KK; k++) wgt[k] *= r;
    }
    __syncthreads();
    float a = 0.f;
    #pragma unroll
    for (int k = 0; k < KK; k++) a += wgt[k] * fe[k][tid];
    att[(long)bn * 256 + tid] = round_tf32(a);
    if (tid < 3) {
        int b = bn >> 11;
        float cg = 0.f;
        #pragma unroll
        for (int k = 0; k < KK; k++)
            cg += wgt[k] * dst_xyz[((long)b*NN + sid[k]) * 3 + tid];
        outC[(long)bn * 3 + tid] = cg;
    }
}

__global__ void k_mlp3(const float* __restrict__ yraw,
                       const float* __restrict__ affS, const float* __restrict__ affQ,
                       const float* __restrict__ gP, const float* __restrict__ bP, float invP,
                       const float* __restrict__ w3, const float* __restrict__ b3,
                       float* __restrict__ outw) {
    int bn = blockIdx.x, tid = threadIdx.x;
    float mu  = affS[tid] * invP;
    float var = fmaxf(affQ[tid] * invP - mu * mu, 0.f);
    float s   = gP[tid] * rsqrtf(var + BNEPS);
    float h   = bP[tid] - mu * s;
    float v = fmaxf(yraw[(long)bn*256 + tid] * s + h, 0.f) * w3[tid];
    #pragma unroll
    for (int o = 16; o > 0; o >>= 1) v += __shfl_down_sync(0xffffffffu, v, o);
    __shared__ float ps[8];
    if ((tid & 31) == 0) ps[tid >> 5] = v;
    __syncthreads();
    if (tid == 0) {
        float s2 = 0.f;
        #pragma unroll
        for (int i = 0; i < 8; i++) s2 += ps[i];
        outw[bn] = 1.f / (1.f + expf(-(s2 + b3[0])));
    }
}

extern "C" void kernel_launch(void* const* d_in, const int* in_sizes, int n_in,
                              void* d_out, int out_size) {
    const float* src_xyz  = (const float*)d_in[0];
    const float* src_desc = (const float*)d_in[1];
    const float* dst_xyz  = (const float*)d_in[2];
    const float* dst_desc = (const float*)d_in[3];
    const float* src_w    = (const float*)d_in[4];
    const float* dst_w    = (const float*)d_in[5];
    const float* c1_W0 = (const float*)d_in[6];
    const float* c1_W  = (const float*)d_in[7];
    const float* c1_g  = (const float*)d_in[8];
    const float* c1_b  = (const float*)d_in[9];
    const float* c2_W0 = (const float*)d_in[10];
    const float* c2_W  = (const float*)d_in[11];
    const float* c2_g  = (const float*)d_in[12];
    const float* c2_b  = (const float*)d_in[13];
    const float* m1_W  = (const float*)d_in[14];
    const float* m1_g  = (const float*)d_in[16];
    const float* m1_b  = (const float*)d_in[17];
    const float* m2_W  = (const float*)d_in[18];
    const float* m2_g  = (const float*)d_in[20];
    const float* m2_b  = (const float*)d_in[21];
    const float* m3_W  = (const float*)d_in[22];
    const float* m3_b  = (const float*)d_in[23];

    float* base = nullptr;
    cudaGetSymbolAddress((void**)&base, g_pool);
    float* srcd   = base + F_SRCD;
    float* dstd   = base + F_DSTD;
    float* nsqS   = base + F_NSQS;
    float* nsqD   = base + F_NSQD;
    float* nrmS   = base + F_NRMS;
    float* nrmD   = base + F_NRMD;
    float* maxDS  = base + F_MAXDS;
    float* maxSD  = base + F_MAXSD;
    float* maxD2  = base + F_MAXD2;
    float* maxS2  = base + F_MAXS2;
    float* nrm2S  = base + F_NRM2S;
    float* nrm2D  = base + F_NRM2D;
    float* sdc    = base + F_SDC;
    float* dsc    = base + F_DSC;
    float* sdn    = base + F_SDN;
    float* dsn    = base + F_DSN;
    float* stat0  = base + F_STATS;
    float* w2p    = base + F_W2P;
    float* wc2    = base + F_WC2;
    float* wc10   = base + F_WC10;
    float* wc1    = base + F_WC1;
    float* wm1    = base + F_WM1;
    float* wm2    = base + F_WM2;
    int*   idx    = (int*)(base + F_IDX);
    int*   sidx   = (int*)(base + F_SIDX);
    float* att    = base + F_ATT;
    float* mb1    = base + F_MB1;
    float* mb2    = base + F_MB2;
    float* srcnbr = base + F_SRCNBR;
    float* inner  = base + F_INNER;
    float* fbuf   = base + F_F;
    float* y0     = base + F_Y0;
    float* y1     = base + F_Y1;
    float* outC   = (float*)d_out;
    float* outW   = (float*)d_out + (long)BB*NN*3;

    auto slot = [&](int i) { return stat0 + (long)i * 1024; };
    const float invPP = 1.f / (float)PP;
    const float invBN = 1.f / (float)BN;

    // ONE setup launch: stat zero + both rounds' max fills + all weight rounding
    k_setup<<<(SETUP_N + 255) / 256, 256>>>(c2_W0, c2_W, c1_W0, c1_W, m1_W, m2_W);

    // A: transpose + norms
    k_transpose_norm<<<dim3(BN, 2), 128>>>(src_desc, dst_desc, srcd, nsqS, nrmS);

    // inner = src . dst with fused cosine maxes
    k_gemm_sim<<<dim3(NN/SGN, NN/SGM, 2), 256>>>(srcd, dstd, inner, nrmS, nrmD, maxDS, maxSD);
    k_knn_desc<<<dim3(NN, BB), 256>>>(inner, nsqS, nsqD, idx);
    k_simgather<<<PP/256, 256>>>(inner, nrmS, nrmD, maxDS, maxSD, idx, sdc, dsc);

    // B: neighborhood descriptors — both clouds batched
    k_knn_xyz<<<dim3(NN, BB, 2), 256>>>(src_xyz, dst_xyz, sidx);
    k_build_nbr_f<<<2*PP, 128>>>(src_xyz, dst_xyz, srcd, sidx, fbuf);
    k_gemm_tc<<<dim3(CC/TCN, (2*PP)/TCM), 256>>>(fbuf, w2p, y0, 2*PP, CC, 144,
        nullptr, nullptr, nullptr, nullptr, 0.f, slot(0), slot(0)+512, PP);
    k_gemm_tc<<<dim3(CC/TCN, (2*PP)/TCM), 256>>>(y0, wc2, y1, 2*PP, CC, CC,
        slot(0), slot(0)+512, c2_g, c2_b, invPP, slot(1), slot(1)+512, PP);
    k_gemm_tc<<<dim3(CC/TCN, (2*PP)/TCM), 256>>>(y1, wc2 + CC*CC, y0, 2*PP, CC, CC,
        slot(1), slot(1)+512, c2_g + CC, c2_b + CC, invPP, slot(2), slot(2)+512, PP);
    k_nbr_final<<<2*BN, 256>>>(y0, slot(2), slot(2)+512, c2_g + 2*CC, c2_b + 2*CC, invPP,
                               sidx, srcd, srcnbr);

    // nbr cosine sims (separate max buffers; fill already done in setup)
    k_rownorm<<<2*BN, 128>>>(srcnbr, nrm2S);
    k_gemm_sim<<<dim3(NN/SGN, NN/SGM, 2), 256>>>(srcnbr, srcnbr + (long)BN*CC, inner,
                                                 nrm2S, nrm2D, maxD2, maxS2);
    k_simgather<<<PP/256, 256>>>(inner, nrm2S, nrm2D, maxD2, maxS2, idx, sdn, dsn);

    // C: main feature conv + attention
    k_build_feats<<<PP, 128>>>(src_xyz, dst_xyz, srcd, dstd, src_w, dst_w,
                               sdc, dsc, sdn, dsn, idx, fbuf);
    k_gemm_tc<<<dim3(256/TCN, PP/TCM), 256>>>(fbuf, wc10, y0, PP, 256, 272,
        nullptr, nullptr, nullptr, nullptr, 0.f, slot(3), slot(3)+512, 0);
    k_gemm_tc<<<dim3(256/TCN, PP/TCM), 256>>>(y0, wc1, y1, PP, 256, 256,
        slot(3), slot(3)+512, c1_g, c1_b, invPP, slot(4), slot(4)+512, 0);
    k_gemm_tc<<<dim3(256/TCN, PP/TCM), 256>>>(y1, wc1 + 256*256, y0, PP, 256, 256,
        slot(4), slot(4)+512, c1_g + 256, c1_b + 256, invPP, slot(5), slot(5)+512, 0);
    k_attention<<<BN, 256>>>(y0, slot(5), slot(5)+512, c1_g + 512, c1_b + 512, invPP,
                             idx, dst_xyz, outC, att);

    // D: MLP head
    k_gemm_tc<<<dim3(256/TCN, BN/TCM), 256>>>(att, wm1, mb1, BN, 256, 256,
        nullptr, nullptr, nullptr, nullptr, 0.f, slot(6), slot(6)+512, 0);
    k_gemm_tc<<<dim3(256/TCN, BN/TCM), 256>>>(mb1, wm2, mb2, BN, 256, 256,
        slot(6), slot(6)+512, m1_g, m1_b, invBN, slot(7), slot(7)+512, 0);
    k_mlp3<<<BN, 256>>>(mb2, slot(7), slot(7)+512, m2_g, m2_b, invBN, m3_W, m3_b, outW);
}